// round 8
// baseline (speedup 1.0000x reference)
#include <cuda_runtime.h>
#include <math.h>

#define N_NODES 50000
#define KNN     8
#define NR      200000   // N * R
#define NT_DEC  1563     // ceil(NR/128)

// ---------------- scratch (device globals) ----------------
__device__ float g_Wc_enc[64 * 128];                 // tf32 [k][ Wd_enc | Wb_enc ]
__device__ float g_W_A[64 * 512];                    // tf32, COLUMN-PERMUTED [k][ Am' | Alv' ]
__device__ float g_W_B[64 * 512];                    // tf32, COLUMN-PERMUTED [k][ Bm' | Blv' ]
__device__ float g_Wdt[64 * 64];                     // tf32 decoder weights
__device__ float g_bmp [256];                        // permuted biases
__device__ float g_blvp[256];
__device__ float g_AB1[(size_t)N_NODES * 128];
__device__ float g_h  [(size_t)N_NODES * 64];        // tf32-rounded at producer
__device__ float g_A2 [(size_t)N_NODES * 512];       // own-part (streamed once)
__device__ float g_B2 [(size_t)N_NODES * 512];       // neighbor-part (gathered 8x)
__device__ float g_z  [(size_t)NT_DEC * 128 * 64];   // tf32; padded to full tiles

__device__ __forceinline__ float to_tf32(float x) {
    unsigned r;
    asm("cvt.rna.tf32.f32 %0, %1;" : "=r"(r) : "f"(x));
    return __uint_as_float(r);
}

// ---------------- weight prep (tf32 pre-rounded, shuffle-permuted columns) ----
// concat([xi, xj-xi]) @ W == xi @ (W_top - W_bot) + xj @ W_bot
// Column position p of the mean/logvar blocks holds channel sigma(p)=(p&63)*4+(p>>6)
// so that gather_ml's point_shuffle output is contiguous.
__global__ void prep_weights(const float* __restrict__ We,
                             const float* __restrict__ Wm,
                             const float* __restrict__ Wlv,
                             const float* __restrict__ Wd,
                             const float* __restrict__ bm,
                             const float* __restrict__ blv) {
    int idx = blockIdx.x * blockDim.x + threadIdx.x;
    if (idx < 64 * 128) {
        int k = idx >> 7, c = idx & 127;
        float v = (c < 64) ? We[k * 64 + c] - We[(64 + k) * 64 + c]
                           : We[(64 + k) * 64 + (c - 64)];
        g_Wc_enc[idx] = to_tf32(v);
    }
    int i2 = idx - 64 * 128;
    if (i2 >= 0 && i2 < 64 * 512) {
        int k = i2 >> 9, c = i2 & 511;
        float a, b;
        if (c < 256) {
            int ch = ((c & 63) << 2) | (c >> 6);           // sigma(c)
            a = Wm[k * 256 + ch] - Wm[(64 + k) * 256 + ch];
            b = Wm[(64 + k) * 256 + ch];
        } else {
            int j = c - 256;
            int ch = ((j & 63) << 2) | (j >> 6);           // sigma(j)
            a = Wlv[k * 256 + ch] - Wlv[(64 + k) * 256 + ch];
            b = Wlv[(64 + k) * 256 + ch];
        }
        g_W_A[i2] = to_tf32(a);
        g_W_B[i2] = to_tf32(b);
    }
    int i3 = idx - 64 * 128 - 64 * 512;
    if (i3 >= 0 && i3 < 64 * 64) g_Wdt[i3] = to_tf32(Wd[i3]);
    int i4 = idx - 64 * 128 - 64 * 512 - 64 * 64;
    if (i4 >= 0 && i4 < 512) {
        int p = i4 & 255;
        int ch = ((p & 63) << 2) | (p >> 6);
        if (i4 < 256) g_bmp[p]  = bm[ch];
        else          g_blvp[p] = blv[ch];
    }
}

// ---------------- tf32 tensor-core GEMM, cp.async double-buffered ----------------
#define XS 68
#define WS 72   // bank = qc*8+qr -> conflict-free b-frag LDS
#define GEMM_SMEM ((128 * XS + 2 * 64 * WS) * 4)   // 71680 B

__device__ __forceinline__ void cp16(unsigned dst, const void* src) {
    asm volatile("cp.async.ca.shared.global [%0], [%1], 16;" :: "r"(dst), "l"(src));
}

template<int NT>
__global__ void __launch_bounds__(256, 2)
gemm_cl(const float* __restrict__ X, const float* __restrict__ W,
        float* __restrict__ C, int M, int Nout, const float* __restrict__ bias)
{
    extern __shared__ float sm[];
    float* xs  = sm;                       // [128][XS]
    float* wsb[2] = { sm + 128 * XS, sm + 128 * XS + 64 * WS };
    const unsigned ws_u0 = (unsigned)__cvta_generic_to_shared(wsb[0]);
    const unsigned ws_u1 = (unsigned)__cvta_generic_to_shared(wsb[1]);

    const int tid  = threadIdx.x;
    const int row0 = blockIdx.x * 128;

    {   // prefetch W tile 0
        const int col0 = blockIdx.y * NT * 64;
        #pragma unroll
        for (int i = 0; i < 4; i++) {
            int f = tid + i * 256, r = f >> 4, c4 = (f & 15) * 4;
            cp16(ws_u0 + (unsigned)(r * WS + c4) * 4,
                 W + (size_t)r * Nout + col0 + c4);
        }
        asm volatile("cp.async.commit_group;");
    }

    // stage X once (tf32 round; idempotent if already rounded)
    #pragma unroll
    for (int i = 0; i < 8; i++) {
        int f  = tid + i * 256;
        int r  = f >> 4;
        int c4 = (f & 15) * 4;
        float4 v = make_float4(0.f, 0.f, 0.f, 0.f);
        if (row0 + r < M) v = *(const float4*)(X + (size_t)(row0 + r) * 64 + c4);
        float* p = xs + r * XS + c4;
        p[0] = to_tf32(v.x); p[1] = to_tf32(v.y);
        p[2] = to_tf32(v.z); p[3] = to_tf32(v.w);
    }
    __syncthreads();

    const int warp = tid >> 5, lane = tid & 31;
    const int wr = warp >> 1, wc = warp & 1;
    const int qr = lane >> 2, qc = lane & 3;

    unsigned areg[8][2][4];
    #pragma unroll
    for (int kb = 0; kb < 8; kb++)
        #pragma unroll
        for (int mi = 0; mi < 2; mi++) {
            const float* p = xs + (wr * 32 + mi * 16 + qr) * XS + kb * 8 + qc;
            areg[kb][mi][0] = __float_as_uint(p[0]);
            areg[kb][mi][1] = __float_as_uint(p[8 * XS]);
            areg[kb][mi][2] = __float_as_uint(p[4]);
            areg[kb][mi][3] = __float_as_uint(p[8 * XS + 4]);
        }

    for (int t = 0; t < NT; t++) {
        if (t + 1 < NT) {
            const int coln = (blockIdx.y * NT + t + 1) * 64;
            unsigned ws_n = ((t + 1) & 1) ? ws_u1 : ws_u0;
            #pragma unroll
            for (int i = 0; i < 4; i++) {
                int f = tid + i * 256, r = f >> 4, c4 = (f & 15) * 4;
                cp16(ws_n + (unsigned)(r * WS + c4) * 4,
                     W + (size_t)r * Nout + coln + c4);
            }
            asm volatile("cp.async.commit_group;");
            asm volatile("cp.async.wait_group 1;");
        } else {
            asm volatile("cp.async.wait_group 0;");
        }
        __syncthreads();

        const float* ws = wsb[t & 1];
        float acc[2][4][4];
        #pragma unroll
        for (int mi = 0; mi < 2; mi++)
            #pragma unroll
            for (int ni = 0; ni < 4; ni++)
                #pragma unroll
                for (int s = 0; s < 4; s++) acc[mi][ni][s] = 0.f;

        #pragma unroll
        for (int kb = 0; kb < 8; kb++) {
            unsigned b[4][2];
            #pragma unroll
            for (int ni = 0; ni < 4; ni++) {
                const float* p = ws + (kb * 8 + qc) * WS + wc * 32 + ni * 8 + qr;
                b[ni][0] = __float_as_uint(p[0]);
                b[ni][1] = __float_as_uint(p[4 * WS]);
            }
            #pragma unroll
            for (int mi = 0; mi < 2; mi++)
                #pragma unroll
                for (int ni = 0; ni < 4; ni++)
                    asm volatile(
                        "mma.sync.aligned.m16n8k8.row.col.f32.tf32.tf32.f32 "
                        "{%0,%1,%2,%3}, {%4,%5,%6,%7}, {%8,%9}, {%0,%1,%2,%3};"
                        : "+f"(acc[mi][ni][0]), "+f"(acc[mi][ni][1]),
                          "+f"(acc[mi][ni][2]), "+f"(acc[mi][ni][3])
                        : "r"(areg[kb][mi][0]), "r"(areg[kb][mi][1]),
                          "r"(areg[kb][mi][2]), "r"(areg[kb][mi][3]),
                          "r"(b[ni][0]), "r"(b[ni][1]));
        }
        __syncthreads();

        const int col0 = (blockIdx.y * NT + t) * 64;
        #pragma unroll
        for (int mi = 0; mi < 2; mi++)
            #pragma unroll
            for (int half = 0; half < 2; half++) {
                int row = row0 + wr * 32 + mi * 16 + qr + half * 8;
                if (row < M) {
                    #pragma unroll
                    for (int ni = 0; ni < 4; ni++) {
                        int col = col0 + wc * 32 + ni * 8 + qc * 2;
                        float2 v;
                        v.x = acc[mi][ni][half * 2 + 0];
                        v.y = acc[mi][ni][half * 2 + 1];
                        if (bias) {
                            float2 bv = *(const float2*)(bias + col);
                            v.x += bv.x; v.y += bv.y;
                        }
                        *(float2*)(C + (size_t)row * Nout + col) = v;
                    }
                }
            }
    }
}

// ---------------- persistent streaming decoder: out = z @ Wd + bd ----------------
// W staged once per block; grid-stride over row tiles; z tiles cp.async
// double-buffered (z is tf32-pre-rounded -> raw byte copy).
#define DEC_SMEM ((2 * 128 * XS + 64 * WS) * 4)   // 88064 B

__global__ void __launch_bounds__(256, 2)
dec_stream(const float* __restrict__ Z, const float* __restrict__ W,
           float* __restrict__ C, const float* __restrict__ bias)
{
    extern __shared__ float sm[];
    float* xb0 = sm;
    float* xb1 = sm + 128 * XS;
    float* ws  = sm + 2 * 128 * XS;
    const unsigned xu[2] = { (unsigned)__cvta_generic_to_shared(xb0),
                             (unsigned)__cvta_generic_to_shared(xb1) };
    const unsigned wu = (unsigned)__cvta_generic_to_shared(ws);

    const int tid = threadIdx.x;

    // stage W (64x64) once + first X tile, one async group
    #pragma unroll
    for (int i = 0; i < 4; i++) {
        int f = tid + i * 256, r = f >> 4, c4 = (f & 15) * 4;
        cp16(wu + (unsigned)(r * WS + c4) * 4, W + r * 64 + c4);
    }
    if (blockIdx.x < NT_DEC) {
        #pragma unroll
        for (int i = 0; i < 8; i++) {
            int f = tid + i * 256, r = f >> 4, c4 = (f & 15) * 4;
            cp16(xu[0] + (unsigned)(r * XS + c4) * 4,
                 Z + (size_t)blockIdx.x * 128 * 64 + r * 64 + c4);
        }
    }
    asm volatile("cp.async.commit_group;");

    const int warp = tid >> 5, lane = tid & 31;
    const int wr = warp >> 1, wc = warp & 1;
    const int qr = lane >> 2, qc = lane & 3;

    int i = 0;
    for (int rt = blockIdx.x; rt < NT_DEC; rt += gridDim.x, i++) {
        int nxt = rt + gridDim.x;
        if (nxt < NT_DEC) {
            unsigned xd = xu[(i + 1) & 1];
            #pragma unroll
            for (int j = 0; j < 8; j++) {
                int f = tid + j * 256, r = f >> 4, c4 = (f & 15) * 4;
                cp16(xd + (unsigned)(r * XS + c4) * 4,
                     Z + (size_t)nxt * 128 * 64 + r * 64 + c4);
            }
            asm volatile("cp.async.commit_group;");
            asm volatile("cp.async.wait_group 1;");
        } else {
            asm volatile("cp.async.wait_group 0;");
        }
        __syncthreads();

        const float* xs = (i & 1) ? xb1 : xb0;
        float acc[2][4][4];
        #pragma unroll
        for (int mi = 0; mi < 2; mi++)
            #pragma unroll
            for (int ni = 0; ni < 4; ni++)
                #pragma unroll
                for (int s = 0; s < 4; s++) acc[mi][ni][s] = 0.f;

        #pragma unroll
        for (int kb = 0; kb < 8; kb++) {
            unsigned a[2][4], b[4][2];
            #pragma unroll
            for (int mi = 0; mi < 2; mi++) {
                const float* p = xs + (wr * 32 + mi * 16 + qr) * XS + kb * 8 + qc;
                a[mi][0] = __float_as_uint(p[0]);
                a[mi][1] = __float_as_uint(p[8 * XS]);
                a[mi][2] = __float_as_uint(p[4]);
                a[mi][3] = __float_as_uint(p[8 * XS + 4]);
            }
            #pragma unroll
            for (int ni = 0; ni < 4; ni++) {
                const float* p = ws + (kb * 8 + qc) * WS + wc * 32 + ni * 8 + qr;
                b[ni][0] = __float_as_uint(p[0]);
                b[ni][1] = __float_as_uint(p[4 * WS]);
            }
            #pragma unroll
            for (int mi = 0; mi < 2; mi++)
                #pragma unroll
                for (int ni = 0; ni < 4; ni++)
                    asm volatile(
                        "mma.sync.aligned.m16n8k8.row.col.f32.tf32.tf32.f32 "
                        "{%0,%1,%2,%3}, {%4,%5,%6,%7}, {%8,%9}, {%0,%1,%2,%3};"
                        : "+f"(acc[mi][ni][0]), "+f"(acc[mi][ni][1]),
                          "+f"(acc[mi][ni][2]), "+f"(acc[mi][ni][3])
                        : "r"(a[mi][0]), "r"(a[mi][1]), "r"(a[mi][2]), "r"(a[mi][3]),
                          "r"(b[ni][0]), "r"(b[ni][1]));
        }
        __syncthreads();   // all reads of xs done before next prefetch overwrites it

        const int row0 = rt * 128;
        #pragma unroll
        for (int mi = 0; mi < 2; mi++)
            #pragma unroll
            for (int half = 0; half < 2; half++) {
                int row = row0 + wr * 32 + mi * 16 + qr + half * 8;
                if (row < NR) {
                    #pragma unroll
                    for (int ni = 0; ni < 4; ni++) {
                        int col = wc * 32 + ni * 8 + qc * 2;
                        float2 v;
                        v.x = acc[mi][ni][half * 2 + 0] + bias[col];
                        v.y = acc[mi][ni][half * 2 + 1] + bias[col + 1];
                        *(float2*)(C + (size_t)row * 64 + col) = v;
                    }
                }
            }
    }
}

// ---------------- encoder gather-max + bias + leaky_relu(0.2) ----------------
__global__ void __launch_bounds__(256)
gather_enc(const int* __restrict__ src, const float* __restrict__ b) {
    __shared__ int ss[32];
    int tid = threadIdx.x;
    if (tid < 32) ss[tid] = src[blockIdx.x * 32 + tid];
    __syncthreads();
    int local = tid >> 6;
    int j     = tid & 63;
    int node  = blockIdx.x * 4 + local;
    float a = __ldcs(g_AB1 + (size_t)node * 128 + j);
    float m = -3.4e38f;
    #pragma unroll
    for (int k = 0; k < KNN; k++) {
        int s = ss[local * 8 + k];
        m = fmaxf(m, g_AB1[(size_t)s * 128 + 64 + j]);
    }
    float v = a + m + b[j];
    v = v > 0.f ? v : 0.2f * v;
    g_h[(size_t)node * 64 + j] = to_tf32(v);
}

// ---------------- mean/logvar gather-max + reparametrize (pre-shuffled) ----------
// Column permutation baked into the weights means output index = node*256 + tid:
// z writes and noise reads are fully contiguous.
__global__ void __launch_bounds__(256)
gather_ml(const int* __restrict__ src, const float* __restrict__ noise) {
    __shared__ int ss[KNN];
    int tid  = threadIdx.x;
    int node = blockIdx.x;
    if (tid < KNN) ss[tid] = src[node * KNN + tid];
    __syncthreads();
    size_t abase = (size_t)node * 512;
    float am  = __ldcs(g_A2 + abase + tid);
    float alv = __ldcs(g_A2 + abase + 256 + tid);
    float mm = -3.4e38f, mlv = -3.4e38f;
    #pragma unroll
    for (int k = 0; k < KNN; k++) {
        size_t sb = (size_t)ss[k] * 512;
        mm  = fmaxf(mm,  g_B2[sb + tid]);
        mlv = fmaxf(mlv, g_B2[sb + 256 + tid]);
    }
    float zm  = am  + mm  + g_bmp[tid];
    float zlv = alv + mlv + g_blvp[tid];
    size_t o = (size_t)node * 256 + tid;
    float nz = __ldcs(noise + o);
    g_z[o] = to_tf32(fmaf(nz, expf(0.5f * zlv), zm));
}

// ---------------- launch ----------------
extern "C" void kernel_launch(void* const* d_in, const int* in_sizes, int n_in,
                              void* d_out, int out_size) {
    const float* x     = (const float*)d_in[0];
    const int*   src   = (const int*)  d_in[1];
    const float* noise = (const float*)d_in[3];
    const float* We    = (const float*)d_in[4];
    const float* be    = (const float*)d_in[5];
    const float* Wm    = (const float*)d_in[6];
    const float* bm    = (const float*)d_in[7];
    const float* Wlv   = (const float*)d_in[8];
    const float* blv   = (const float*)d_in[9];
    const float* Wd    = (const float*)d_in[10];
    const float* bd    = (const float*)d_in[11];
    float* out = (float*)d_out;

    float *pWcE, *pWA, *pWB, *pWdt, *pAB1, *pH, *pA2, *pB2, *pZ;
    cudaGetSymbolAddress((void**)&pWcE, g_Wc_enc);
    cudaGetSymbolAddress((void**)&pWA,  g_W_A);
    cudaGetSymbolAddress((void**)&pWB,  g_W_B);
    cudaGetSymbolAddress((void**)&pWdt, g_Wdt);
    cudaGetSymbolAddress((void**)&pAB1, g_AB1);
    cudaGetSymbolAddress((void**)&pH,   g_h);
    cudaGetSymbolAddress((void**)&pA2,  g_A2);
    cudaGetSymbolAddress((void**)&pB2,  g_B2);
    cudaGetSymbolAddress((void**)&pZ,   g_z);

    cudaFuncSetAttribute(gemm_cl<2>, cudaFuncAttributeMaxDynamicSharedMemorySize, GEMM_SMEM);
    cudaFuncSetAttribute(gemm_cl<4>, cudaFuncAttributeMaxDynamicSharedMemorySize, GEMM_SMEM);
    cudaFuncSetAttribute(dec_stream, cudaFuncAttributeMaxDynamicSharedMemorySize, DEC_SMEM);

    // 1. combined weights (tf32, shuffle-permuted)
    prep_weights<<<179, 256>>>(We, Wm, Wlv, Wd, bm, blv);
    // 2. AB1 = x @ [Wd_enc | Wb_enc]   (50000 x 128)
    gemm_cl<2><<<dim3(391, 1), 256, GEMM_SMEM>>>(x, pWcE, pAB1, N_NODES, 128, nullptr);
    // 3. h = leaky(A + max_k B[src] + b)   (tf32-rounded)
    gather_enc<<<12500, 256>>>(src, be);
    // 4a. A2 = h @ [Am'|Alv']  (50000 x 512)
    gemm_cl<4><<<dim3(391, 2), 256, GEMM_SMEM>>>(pH, pWA, pA2, N_NODES, 512, nullptr);
    // 4b. B2 = h @ [Bm'|Blv']  (50000 x 512)
    gemm_cl<4><<<dim3(391, 2), 256, GEMM_SMEM>>>(pH, pWB, pB2, N_NODES, 512, nullptr);
    // 5. gather-max x2 + reparametrize -> z (contiguous writes; tf32-rounded)
    gather_ml<<<N_NODES, 256>>>(src, noise);
    // 6. out = z @ W_dec + b_dec  (persistent streaming)
    dec_stream<<<296, 256, DEC_SMEM>>>(pZ, pWdt, out, bd);
}

// round 9
// speedup vs baseline: 1.0419x; 1.0419x over previous
#include <cuda_runtime.h>
#include <math.h>

#define N_NODES 50000
#define KNN     8
#define NR      200000   // N * R

// ---------------- scratch (device globals) ----------------
__device__ float g_Wc_enc[64 * 128];                 // tf32 [k][ Wd_enc | Wb_enc ]
__device__ float g_W_AB[64 * 1024];                  // tf32, permuted: [k][ Am'|Alv' | Bm'|Blv' ]
__device__ float g_Wdt[64 * 64];                     // tf32 decoder weights
__device__ float g_bmp [256];                        // permuted biases
__device__ float g_blvp[256];
__device__ float g_AB1[(size_t)N_NODES * 128];
__device__ float g_h  [(size_t)N_NODES * 64];        // tf32-rounded at producer
__device__ float g_AB2[(size_t)N_NODES * 1024];      // [ own(512) | neighbor(512) ]
__device__ float g_z  [(size_t)NR * 64];             // tf32-rounded, shuffle-contiguous

__device__ __forceinline__ float to_tf32(float x) {
    unsigned r;
    asm("cvt.rna.tf32.f32 %0, %1;" : "=r"(r) : "f"(x));
    return __uint_as_float(r);
}

// ---------------- weight prep (tf32, shuffle-permuted columns) ----------------
// concat([xi, xj-xi]) @ W == xi @ (W_top - W_bot) + xj @ W_bot
// Column p of each 256-block holds channel sigma(p)=(p&63)*4+(p>>6) so that the
// point_shuffle output is contiguous at the gather.
__global__ void prep_weights(const float* __restrict__ We,
                             const float* __restrict__ Wm,
                             const float* __restrict__ Wlv,
                             const float* __restrict__ Wd,
                             const float* __restrict__ bm,
                             const float* __restrict__ blv) {
    int idx = blockIdx.x * blockDim.x + threadIdx.x;
    if (idx < 64 * 128) {
        int k = idx >> 7, c = idx & 127;
        float v = (c < 64) ? We[k * 64 + c] - We[(64 + k) * 64 + c]
                           : We[(64 + k) * 64 + (c - 64)];
        g_Wc_enc[idx] = to_tf32(v);
    }
    int i2 = idx - 64 * 128;
    if (i2 >= 0 && i2 < 64 * 1024) {
        int k = i2 >> 10, c = i2 & 1023;
        int half = c >> 9;                 // 0 = own(A), 1 = neighbor(B)
        int cc   = c & 511;
        const float* Wsrc = (cc < 256) ? Wm : Wlv;
        int j  = cc & 255;
        int ch = ((j & 63) << 2) | (j >> 6);   // sigma
        float v;
        if (half == 0) v = Wsrc[k * 256 + ch] - Wsrc[(64 + k) * 256 + ch];
        else           v = Wsrc[(64 + k) * 256 + ch];
        g_W_AB[i2] = to_tf32(v);
    }
    int i3 = idx - 64 * 128 - 64 * 1024;
    if (i3 >= 0 && i3 < 64 * 64) g_Wdt[i3] = to_tf32(Wd[i3]);
    int i4 = idx - 64 * 128 - 64 * 1024 - 64 * 64;
    if (i4 >= 0 && i4 < 512) {
        int p = i4 & 255;
        int ch = ((p & 63) << 2) | (p >> 6);
        if (i4 < 256) g_bmp[p]  = bm[ch];
        else          g_blvp[p] = blv[ch];
    }
}

// ---------------- tf32 tensor-core GEMM, cp.async double-buffered ----------------
// C[M,Nout] = X[M,64] @ W[64,Nout] (+bias). W tf32-pre-rounded.
// 128 rows x (NT*64) cols per block; X staged once, a-frags hoisted to regs;
// W column tiles double-buffered via cp.async.
#define XS 68
#define WS 72   // bank = qc*8+qr -> conflict-free b-frag LDS
#define GEMM_SMEM ((128 * XS + 2 * 64 * WS) * 4)   // 71680 B

__device__ __forceinline__ void cp16(unsigned dst, const void* src) {
    asm volatile("cp.async.ca.shared.global [%0], [%1], 16;" :: "r"(dst), "l"(src));
}

template<int NT>
__global__ void __launch_bounds__(256, 2)
gemm_cl(const float* __restrict__ X, const float* __restrict__ W,
        float* __restrict__ C, int M, int Nout, const float* __restrict__ bias)
{
    extern __shared__ float sm[];
    float* xs  = sm;                       // [128][XS]
    float* wsb[2] = { sm + 128 * XS, sm + 128 * XS + 64 * WS };
    const unsigned ws_u0 = (unsigned)__cvta_generic_to_shared(wsb[0]);
    const unsigned ws_u1 = (unsigned)__cvta_generic_to_shared(wsb[1]);

    const int tid  = threadIdx.x;
    const int row0 = blockIdx.x * 128;

    {   // prefetch W tile 0
        const int col0 = blockIdx.y * NT * 64;
        #pragma unroll
        for (int i = 0; i < 4; i++) {
            int f = tid + i * 256, r = f >> 4, c4 = (f & 15) * 4;
            cp16(ws_u0 + (unsigned)(r * WS + c4) * 4,
                 W + (size_t)r * Nout + col0 + c4);
        }
        asm volatile("cp.async.commit_group;");
    }

    // stage X once (tf32 round; idempotent if already rounded)
    #pragma unroll
    for (int i = 0; i < 8; i++) {
        int f  = tid + i * 256;
        int r  = f >> 4;
        int c4 = (f & 15) * 4;
        float4 v = make_float4(0.f, 0.f, 0.f, 0.f);
        if (row0 + r < M) v = *(const float4*)(X + (size_t)(row0 + r) * 64 + c4);
        float* p = xs + r * XS + c4;
        p[0] = to_tf32(v.x); p[1] = to_tf32(v.y);
        p[2] = to_tf32(v.z); p[3] = to_tf32(v.w);
    }
    __syncthreads();

    const int warp = tid >> 5, lane = tid & 31;
    const int wr = warp >> 1, wc = warp & 1;
    const int qr = lane >> 2, qc = lane & 3;

    unsigned areg[8][2][4];
    #pragma unroll
    for (int kb = 0; kb < 8; kb++)
        #pragma unroll
        for (int mi = 0; mi < 2; mi++) {
            const float* p = xs + (wr * 32 + mi * 16 + qr) * XS + kb * 8 + qc;
            areg[kb][mi][0] = __float_as_uint(p[0]);
            areg[kb][mi][1] = __float_as_uint(p[8 * XS]);
            areg[kb][mi][2] = __float_as_uint(p[4]);
            areg[kb][mi][3] = __float_as_uint(p[8 * XS + 4]);
        }

    for (int t = 0; t < NT; t++) {
        if (t + 1 < NT) {
            const int coln = (blockIdx.y * NT + t + 1) * 64;
            unsigned ws_n = ((t + 1) & 1) ? ws_u1 : ws_u0;
            #pragma unroll
            for (int i = 0; i < 4; i++) {
                int f = tid + i * 256, r = f >> 4, c4 = (f & 15) * 4;
                cp16(ws_n + (unsigned)(r * WS + c4) * 4,
                     W + (size_t)r * Nout + coln + c4);
            }
            asm volatile("cp.async.commit_group;");
            asm volatile("cp.async.wait_group 1;");
        } else {
            asm volatile("cp.async.wait_group 0;");
        }
        __syncthreads();

        const float* ws = wsb[t & 1];
        float acc[2][4][4];
        #pragma unroll
        for (int mi = 0; mi < 2; mi++)
            #pragma unroll
            for (int ni = 0; ni < 4; ni++)
                #pragma unroll
                for (int s = 0; s < 4; s++) acc[mi][ni][s] = 0.f;

        #pragma unroll
        for (int kb = 0; kb < 8; kb++) {
            unsigned b[4][2];
            #pragma unroll
            for (int ni = 0; ni < 4; ni++) {
                const float* p = ws + (kb * 8 + qc) * WS + wc * 32 + ni * 8 + qr;
                b[ni][0] = __float_as_uint(p[0]);
                b[ni][1] = __float_as_uint(p[4 * WS]);
            }
            #pragma unroll
            for (int mi = 0; mi < 2; mi++)
                #pragma unroll
                for (int ni = 0; ni < 4; ni++)
                    asm volatile(
                        "mma.sync.aligned.m16n8k8.row.col.f32.tf32.tf32.f32 "
                        "{%0,%1,%2,%3}, {%4,%5,%6,%7}, {%8,%9}, {%0,%1,%2,%3};"
                        : "+f"(acc[mi][ni][0]), "+f"(acc[mi][ni][1]),
                          "+f"(acc[mi][ni][2]), "+f"(acc[mi][ni][3])
                        : "r"(areg[kb][mi][0]), "r"(areg[kb][mi][1]),
                          "r"(areg[kb][mi][2]), "r"(areg[kb][mi][3]),
                          "r"(b[ni][0]), "r"(b[ni][1]));
        }
        __syncthreads();

        const int col0 = (blockIdx.y * NT + t) * 64;
        #pragma unroll
        for (int mi = 0; mi < 2; mi++)
            #pragma unroll
            for (int half = 0; half < 2; half++) {
                int row = row0 + wr * 32 + mi * 16 + qr + half * 8;
                if (row < M) {
                    #pragma unroll
                    for (int ni = 0; ni < 4; ni++) {
                        int col = col0 + wc * 32 + ni * 8 + qc * 2;
                        float2 v;
                        v.x = acc[mi][ni][half * 2 + 0];
                        v.y = acc[mi][ni][half * 2 + 1];
                        if (bias) {
                            float2 bv = *(const float2*)(bias + col);
                            v.x += bv.x; v.y += bv.y;
                        }
                        *(float2*)(C + (size_t)row * Nout + col) = v;
                    }
                }
            }
    }
}

// ---------------- encoder gather-max + bias + leaky_relu(0.2) ----------------
__global__ void __launch_bounds__(256)
gather_enc(const int* __restrict__ src, const float* __restrict__ b) {
    __shared__ int ss[32];
    int tid = threadIdx.x;
    if (tid < 32) ss[tid] = src[blockIdx.x * 32 + tid];
    __syncthreads();
    int local = tid >> 6;
    int j     = tid & 63;
    int node  = blockIdx.x * 4 + local;
    float a = __ldcs(g_AB1 + (size_t)node * 128 + j);
    float m = -3.4e38f;
    #pragma unroll
    for (int k = 0; k < KNN; k++) {
        int s = ss[local * 8 + k];
        m = fmaxf(m, g_AB1[(size_t)s * 128 + 64 + j]);
    }
    float v = a + m + b[j];
    v = v > 0.f ? v : 0.2f * v;
    g_h[(size_t)node * 64 + j] = to_tf32(v);
}

// ---------------- mean/logvar gather-max + reparametrize (pre-shuffled) ----------
// Weights permuted -> output index node*256 + tid: z writes and noise reads
// fully contiguous. AB2 row: [ own mean(256) | own lv(256) | nb mean(256) | nb lv(256) ].
__global__ void __launch_bounds__(256)
gather_ml(const int* __restrict__ src, const float* __restrict__ noise) {
    __shared__ int ss[KNN];
    int tid  = threadIdx.x;
    int node = blockIdx.x;
    if (tid < KNN) ss[tid] = src[node * KNN + tid];
    __syncthreads();
    size_t abase = (size_t)node * 1024;
    float am  = __ldcs(g_AB2 + abase + tid);
    float alv = __ldcs(g_AB2 + abase + 256 + tid);
    float mm = -3.4e38f, mlv = -3.4e38f;
    #pragma unroll
    for (int k = 0; k < KNN; k++) {
        size_t sb = (size_t)ss[k] * 1024 + 512;
        mm  = fmaxf(mm,  g_AB2[sb + tid]);
        mlv = fmaxf(mlv, g_AB2[sb + 256 + tid]);
    }
    float zm  = am  + mm  + g_bmp[tid];
    float zlv = alv + mlv + g_blvp[tid];
    size_t o = (size_t)node * 256 + tid;
    float nz = __ldcs(noise + o);
    g_z[o] = to_tf32(fmaf(nz, expf(0.5f * zlv), zm));
}

// ---------------- launch ----------------
extern "C" void kernel_launch(void* const* d_in, const int* in_sizes, int n_in,
                              void* d_out, int out_size) {
    const float* x     = (const float*)d_in[0];
    const int*   src   = (const int*)  d_in[1];
    const float* noise = (const float*)d_in[3];
    const float* We    = (const float*)d_in[4];
    const float* be    = (const float*)d_in[5];
    const float* Wm    = (const float*)d_in[6];
    const float* bm    = (const float*)d_in[7];
    const float* Wlv   = (const float*)d_in[8];
    const float* blv   = (const float*)d_in[9];
    const float* Wd    = (const float*)d_in[10];
    const float* bd    = (const float*)d_in[11];
    float* out = (float*)d_out;

    float *pWcE, *pWAB, *pWdt, *pAB1, *pH, *pAB2, *pZ;
    cudaGetSymbolAddress((void**)&pWcE, g_Wc_enc);
    cudaGetSymbolAddress((void**)&pWAB, g_W_AB);
    cudaGetSymbolAddress((void**)&pWdt, g_Wdt);
    cudaGetSymbolAddress((void**)&pAB1, g_AB1);
    cudaGetSymbolAddress((void**)&pH,   g_h);
    cudaGetSymbolAddress((void**)&pAB2, g_AB2);
    cudaGetSymbolAddress((void**)&pZ,   g_z);

    cudaFuncSetAttribute(gemm_cl<1>, cudaFuncAttributeMaxDynamicSharedMemorySize, GEMM_SMEM);
    cudaFuncSetAttribute(gemm_cl<2>, cudaFuncAttributeMaxDynamicSharedMemorySize, GEMM_SMEM);
    cudaFuncSetAttribute(gemm_cl<8>, cudaFuncAttributeMaxDynamicSharedMemorySize, GEMM_SMEM);

    // 1. combined weights (tf32, shuffle-permuted)
    prep_weights<<<308, 256>>>(We, Wm, Wlv, Wd, bm, blv);
    // 2. AB1 = x @ [Wd_enc | Wb_enc]   (50000 x 128)
    gemm_cl<2><<<dim3(391, 1), 256, GEMM_SMEM>>>(x, pWcE, pAB1, N_NODES, 128, nullptr);
    // 3. h = leaky(A + max_k B[src] + b)   (tf32-rounded)
    gather_enc<<<12500, 256>>>(src, be);
    // 4. AB2 = h @ [Am'|Alv'|Bm'|Blv']  (50000 x 1024, single merged launch)
    gemm_cl<8><<<dim3(391, 2), 256, GEMM_SMEM>>>(pH, pWAB, pAB2, N_NODES, 1024, nullptr);
    // 5. gather-max x2 + reparametrize -> z (contiguous; tf32-rounded)
    gather_ml<<<N_NODES, 256>>>(src, noise);
    // 6. out = z @ W_dec + b_dec  (proven 1563-block form)
    gemm_cl<1><<<dim3(1563, 1), 256, GEMM_SMEM>>>(pZ, pWdt, out, NR, 64, bd);
}

// round 10
// speedup vs baseline: 1.1732x; 1.1261x over previous
#include <cuda_runtime.h>
#include <cuda_fp16.h>
#include <math.h>

#define N_NODES 50000
#define KNN     8
#define NR      200000   // N * R
#define NT_DEC  1563     // ceil(NR/128)

// ---------------- scratch (device globals) ----------------
__device__ float  g_Wc_enc[64 * 128];                // tf32 [k][ Wd_enc | Wb_enc ]
__device__ float  g_W_AB[64 * 1024];                 // tf32, permuted: [k][ Am'|Alv' | Bm'|Blv' ]
__device__ float  g_Wdt[64 * 64];                    // tf32 decoder weights
__device__ float  g_bmp [256];                       // permuted biases
__device__ float  g_blvp[256];
__device__ float  g_AB1[(size_t)N_NODES * 128];
__device__ float  g_h  [(size_t)N_NODES * 64];       // tf32-rounded at producer
__device__ __half g_AB2h[(size_t)N_NODES * 1024];    // fp16: [ own(512) | neighbor(512) ] 102MB
__device__ __half g_zh [(size_t)NT_DEC * 128 * 64];  // fp16 z, padded to full tiles (25.6MB)

__device__ __forceinline__ float to_tf32(float x) {
    unsigned r;
    asm("cvt.rna.tf32.f32 %0, %1;" : "=r"(r) : "f"(x));
    return __uint_as_float(r);
}

// ---------------- weight prep (tf32, shuffle-permuted columns) ----------------
// concat([xi, xj-xi]) @ W == xi @ (W_top - W_bot) + xj @ W_bot
// Column p of each 256-block holds channel sigma(p)=(p&63)*4+(p>>6) so that the
// point_shuffle output is contiguous at the gather.
__global__ void prep_weights(const float* __restrict__ We,
                             const float* __restrict__ Wm,
                             const float* __restrict__ Wlv,
                             const float* __restrict__ Wd,
                             const float* __restrict__ bm,
                             const float* __restrict__ blv) {
    int idx = blockIdx.x * blockDim.x + threadIdx.x;
    if (idx < 64 * 128) {
        int k = idx >> 7, c = idx & 127;
        float v = (c < 64) ? We[k * 64 + c] - We[(64 + k) * 64 + c]
                           : We[(64 + k) * 64 + (c - 64)];
        g_Wc_enc[idx] = to_tf32(v);
    }
    int i2 = idx - 64 * 128;
    if (i2 >= 0 && i2 < 64 * 1024) {
        int k = i2 >> 10, c = i2 & 1023;
        int half = c >> 9;                 // 0 = own(A), 1 = neighbor(B)
        int cc   = c & 511;
        const float* Wsrc = (cc < 256) ? Wm : Wlv;
        int j  = cc & 255;
        int ch = ((j & 63) << 2) | (j >> 6);   // sigma
        float v;
        if (half == 0) v = Wsrc[k * 256 + ch] - Wsrc[(64 + k) * 256 + ch];
        else           v = Wsrc[(64 + k) * 256 + ch];
        g_W_AB[i2] = to_tf32(v);
    }
    int i3 = idx - 64 * 128 - 64 * 1024;
    if (i3 >= 0 && i3 < 64 * 64) g_Wdt[i3] = to_tf32(Wd[i3]);
    int i4 = idx - 64 * 128 - 64 * 1024 - 64 * 64;
    if (i4 >= 0 && i4 < 512) {
        int p = i4 & 255;
        int ch = ((p & 63) << 2) | (p >> 6);
        if (i4 < 256) g_bmp[p]  = bm[ch];
        else          g_blvp[p] = blv[ch];
    }
}

// ---------------- tf32 tensor-core GEMM, cp.async double-buffered ----------------
// C[M,Nout] = X[M,64] @ W[64,Nout] (+bias). W tf32-pre-rounded.
// HALF_OUT: store results as fp16 (C cast to __half*).
#define XS 68
#define WS 72   // bank = qc*8+qr -> conflict-free b-frag LDS
#define GEMM_SMEM ((128 * XS + 2 * 64 * WS) * 4)   // 71680 B

__device__ __forceinline__ void cp16(unsigned dst, const void* src) {
    asm volatile("cp.async.ca.shared.global [%0], [%1], 16;" :: "r"(dst), "l"(src));
}

template<int NT, bool HALF_OUT>
__global__ void __launch_bounds__(256, 2)
gemm_cl(const float* __restrict__ X, const float* __restrict__ W,
        void* __restrict__ Cv, int M, int Nout, const float* __restrict__ bias)
{
    extern __shared__ float sm[];
    float* xs  = sm;                       // [128][XS]
    float* wsb[2] = { sm + 128 * XS, sm + 128 * XS + 64 * WS };
    const unsigned ws_u0 = (unsigned)__cvta_generic_to_shared(wsb[0]);
    const unsigned ws_u1 = (unsigned)__cvta_generic_to_shared(wsb[1]);

    const int tid  = threadIdx.x;
    const int row0 = blockIdx.x * 128;

    {   // prefetch W tile 0
        const int col0 = blockIdx.y * NT * 64;
        #pragma unroll
        for (int i = 0; i < 4; i++) {
            int f = tid + i * 256, r = f >> 4, c4 = (f & 15) * 4;
            cp16(ws_u0 + (unsigned)(r * WS + c4) * 4,
                 W + (size_t)r * Nout + col0 + c4);
        }
        asm volatile("cp.async.commit_group;");
    }

    // stage X once (tf32 round; idempotent if already rounded)
    #pragma unroll
    for (int i = 0; i < 8; i++) {
        int f  = tid + i * 256;
        int r  = f >> 4;
        int c4 = (f & 15) * 4;
        float4 v = make_float4(0.f, 0.f, 0.f, 0.f);
        if (row0 + r < M) v = *(const float4*)(X + (size_t)(row0 + r) * 64 + c4);
        float* p = xs + r * XS + c4;
        p[0] = to_tf32(v.x); p[1] = to_tf32(v.y);
        p[2] = to_tf32(v.z); p[3] = to_tf32(v.w);
    }
    __syncthreads();

    const int warp = tid >> 5, lane = tid & 31;
    const int wr = warp >> 1, wc = warp & 1;
    const int qr = lane >> 2, qc = lane & 3;

    unsigned areg[8][2][4];
    #pragma unroll
    for (int kb = 0; kb < 8; kb++)
        #pragma unroll
        for (int mi = 0; mi < 2; mi++) {
            const float* p = xs + (wr * 32 + mi * 16 + qr) * XS + kb * 8 + qc;
            areg[kb][mi][0] = __float_as_uint(p[0]);
            areg[kb][mi][1] = __float_as_uint(p[8 * XS]);
            areg[kb][mi][2] = __float_as_uint(p[4]);
            areg[kb][mi][3] = __float_as_uint(p[8 * XS + 4]);
        }

    for (int t = 0; t < NT; t++) {
        if (t + 1 < NT) {
            const int coln = (blockIdx.y * NT + t + 1) * 64;
            unsigned ws_n = ((t + 1) & 1) ? ws_u1 : ws_u0;
            #pragma unroll
            for (int i = 0; i < 4; i++) {
                int f = tid + i * 256, r = f >> 4, c4 = (f & 15) * 4;
                cp16(ws_n + (unsigned)(r * WS + c4) * 4,
                     W + (size_t)r * Nout + coln + c4);
            }
            asm volatile("cp.async.commit_group;");
            asm volatile("cp.async.wait_group 1;");
        } else {
            asm volatile("cp.async.wait_group 0;");
        }
        __syncthreads();

        const float* ws = wsb[t & 1];
        float acc[2][4][4];
        #pragma unroll
        for (int mi = 0; mi < 2; mi++)
            #pragma unroll
            for (int ni = 0; ni < 4; ni++)
                #pragma unroll
                for (int s = 0; s < 4; s++) acc[mi][ni][s] = 0.f;

        #pragma unroll
        for (int kb = 0; kb < 8; kb++) {
            unsigned b[4][2];
            #pragma unroll
            for (int ni = 0; ni < 4; ni++) {
                const float* p = ws + (kb * 8 + qc) * WS + wc * 32 + ni * 8 + qr;
                b[ni][0] = __float_as_uint(p[0]);
                b[ni][1] = __float_as_uint(p[4 * WS]);
            }
            #pragma unroll
            for (int mi = 0; mi < 2; mi++)
                #pragma unroll
                for (int ni = 0; ni < 4; ni++)
                    asm volatile(
                        "mma.sync.aligned.m16n8k8.row.col.f32.tf32.tf32.f32 "
                        "{%0,%1,%2,%3}, {%4,%5,%6,%7}, {%8,%9}, {%0,%1,%2,%3};"
                        : "+f"(acc[mi][ni][0]), "+f"(acc[mi][ni][1]),
                          "+f"(acc[mi][ni][2]), "+f"(acc[mi][ni][3])
                        : "r"(areg[kb][mi][0]), "r"(areg[kb][mi][1]),
                          "r"(areg[kb][mi][2]), "r"(areg[kb][mi][3]),
                          "r"(b[ni][0]), "r"(b[ni][1]));
        }
        __syncthreads();

        const int col0 = (blockIdx.y * NT + t) * 64;
        #pragma unroll
        for (int mi = 0; mi < 2; mi++)
            #pragma unroll
            for (int half = 0; half < 2; half++) {
                int row = row0 + wr * 32 + mi * 16 + qr + half * 8;
                if (row < M) {
                    #pragma unroll
                    for (int ni = 0; ni < 4; ni++) {
                        int col = col0 + wc * 32 + ni * 8 + qc * 2;
                        float vx = acc[mi][ni][half * 2 + 0];
                        float vy = acc[mi][ni][half * 2 + 1];
                        if (bias) {
                            float2 bv = *(const float2*)(bias + col);
                            vx += bv.x; vy += bv.y;
                        }
                        if (HALF_OUT) {
                            *(__half2*)((__half*)Cv + (size_t)row * Nout + col) =
                                __floats2half2_rn(vx, vy);
                        } else {
                            *(float2*)((float*)Cv + (size_t)row * Nout + col) =
                                make_float2(vx, vy);
                        }
                    }
                }
            }
    }
}

// ---------------- decoder GEMM: out[NR,64] = z(fp16) @ Wd + bd ----------------
// Static smem: z tile as fp16 (exact convert back to tf32 at hoist).
#define XSH 72   // half stride per row (144 B, 16B-aligned)

__global__ void __launch_bounds__(256, 2)
gemm_dec(const __half* __restrict__ Z, const float* __restrict__ W,
         float* __restrict__ C, const float* __restrict__ bias)
{
    __shared__ __half xsh[128 * XSH];
    __shared__ float  ws [64 * WS];
    const unsigned xu = (unsigned)__cvta_generic_to_shared(xsh);
    const unsigned wu = (unsigned)__cvta_generic_to_shared(ws);

    const int tid  = threadIdx.x;
    const int row0 = blockIdx.x * 128;

    // stage W (64x64 floats) + z tile (128x64 halves), one async group
    #pragma unroll
    for (int i = 0; i < 4; i++) {
        int f = tid + i * 256, r = f >> 4, c4 = (f & 15) * 4;
        cp16(wu + (unsigned)(r * WS + c4) * 4, W + r * 64 + c4);
    }
    #pragma unroll
    for (int i = 0; i < 4; i++) {
        int f = tid + i * 256, r = f >> 3, c8 = (f & 7) * 8;   // 8 halves = 16B
        cp16(xu + (unsigned)(r * XSH + c8) * 2,
             Z + (size_t)row0 * 64 + r * 64 + c8);
    }
    asm volatile("cp.async.commit_group;");
    asm volatile("cp.async.wait_group 0;");
    __syncthreads();

    const int warp = tid >> 5, lane = tid & 31;
    const int wr = warp >> 1, wc = warp & 1;
    const int qr = lane >> 2, qc = lane & 3;

    float acc[2][4][4];
    #pragma unroll
    for (int mi = 0; mi < 2; mi++)
        #pragma unroll
        for (int ni = 0; ni < 4; ni++)
            #pragma unroll
            for (int s = 0; s < 4; s++) acc[mi][ni][s] = 0.f;

    #pragma unroll
    for (int kb = 0; kb < 8; kb++) {
        unsigned a[2][4], b[4][2];
        #pragma unroll
        for (int mi = 0; mi < 2; mi++) {
            const __half* p = xsh + (wr * 32 + mi * 16 + qr) * XSH + kb * 8 + qc;
            a[mi][0] = __float_as_uint(__half2float(p[0]));
            a[mi][1] = __float_as_uint(__half2float(p[8 * XSH]));
            a[mi][2] = __float_as_uint(__half2float(p[4]));
            a[mi][3] = __float_as_uint(__half2float(p[8 * XSH + 4]));
        }
        #pragma unroll
        for (int ni = 0; ni < 4; ni++) {
            const float* p = ws + (kb * 8 + qc) * WS + wc * 32 + ni * 8 + qr;
            b[ni][0] = __float_as_uint(p[0]);
            b[ni][1] = __float_as_uint(p[4 * WS]);
        }
        #pragma unroll
        for (int mi = 0; mi < 2; mi++)
            #pragma unroll
            for (int ni = 0; ni < 4; ni++)
                asm volatile(
                    "mma.sync.aligned.m16n8k8.row.col.f32.tf32.tf32.f32 "
                    "{%0,%1,%2,%3}, {%4,%5,%6,%7}, {%8,%9}, {%0,%1,%2,%3};"
                    : "+f"(acc[mi][ni][0]), "+f"(acc[mi][ni][1]),
                      "+f"(acc[mi][ni][2]), "+f"(acc[mi][ni][3])
                    : "r"(a[mi][0]), "r"(a[mi][1]), "r"(a[mi][2]), "r"(a[mi][3]),
                      "r"(b[ni][0]), "r"(b[ni][1]));
    }

    #pragma unroll
    for (int mi = 0; mi < 2; mi++)
        #pragma unroll
        for (int half = 0; half < 2; half++) {
            int row = row0 + wr * 32 + mi * 16 + qr + half * 8;
            if (row < NR) {
                #pragma unroll
                for (int ni = 0; ni < 4; ni++) {
                    int col = wc * 32 + ni * 8 + qc * 2;
                    float2 v;
                    v.x = acc[mi][ni][half * 2 + 0] + bias[col];
                    v.y = acc[mi][ni][half * 2 + 1] + bias[col + 1];
                    *(float2*)(C + (size_t)row * 64 + col) = v;
                }
            }
        }
}

// ---------------- encoder gather-max + bias + leaky_relu(0.2) ----------------
__global__ void __launch_bounds__(256)
gather_enc(const int* __restrict__ src, const float* __restrict__ b) {
    __shared__ int ss[32];
    int tid = threadIdx.x;
    if (tid < 32) ss[tid] = src[blockIdx.x * 32 + tid];
    __syncthreads();
    int local = tid >> 6;
    int j     = tid & 63;
    int node  = blockIdx.x * 4 + local;
    float a = __ldcs(g_AB1 + (size_t)node * 128 + j);
    float m = -3.4e38f;
    #pragma unroll
    for (int k = 0; k < KNN; k++) {
        int s = ss[local * 8 + k];
        m = fmaxf(m, g_AB1[(size_t)s * 128 + 64 + j]);
    }
    float v = a + m + b[j];
    v = v > 0.f ? v : 0.2f * v;
    g_h[(size_t)node * 64 + j] = to_tf32(v);
}

// ---------------- mean/logvar gather-max + reparametrize (pre-shuffled) ----------
// fp16 AB2 in, fp16 z out; output index node*256 + tid is fully contiguous.
__global__ void __launch_bounds__(256)
gather_ml(const int* __restrict__ src, const float* __restrict__ noise) {
    __shared__ int ss[KNN];
    int tid  = threadIdx.x;
    int node = blockIdx.x;
    if (tid < KNN) ss[tid] = src[node * KNN + tid];
    __syncthreads();
    size_t abase = (size_t)node * 1024;
    float am  = __half2float(__ldcs(g_AB2h + abase + tid));        // own: streamed
    float alv = __half2float(__ldcs(g_AB2h + abase + 256 + tid));
    float mm = -3.4e38f, mlv = -3.4e38f;
    #pragma unroll
    for (int k = 0; k < KNN; k++) {
        size_t sb = (size_t)ss[k] * 1024 + 512;
        mm  = fmaxf(mm,  __half2float(g_AB2h[sb + tid]));          // neighbor: L2-resident
        mlv = fmaxf(mlv, __half2float(g_AB2h[sb + 256 + tid]));
    }
    float zm  = am  + mm  + g_bmp[tid];
    float zlv = alv + mlv + g_blvp[tid];
    size_t o = (size_t)node * 256 + tid;
    float nz = __ldcs(noise + o);
    g_zh[o] = __float2half_rn(fmaf(nz, expf(0.5f * zlv), zm));
}

// ---------------- launch ----------------
extern "C" void kernel_launch(void* const* d_in, const int* in_sizes, int n_in,
                              void* d_out, int out_size) {
    const float* x     = (const float*)d_in[0];
    const int*   src   = (const int*)  d_in[1];
    const float* noise = (const float*)d_in[3];
    const float* We    = (const float*)d_in[4];
    const float* be    = (const float*)d_in[5];
    const float* Wm    = (const float*)d_in[6];
    const float* bm    = (const float*)d_in[7];
    const float* Wlv   = (const float*)d_in[8];
    const float* blv   = (const float*)d_in[9];
    const float* Wd    = (const float*)d_in[10];
    const float* bd    = (const float*)d_in[11];
    float* out = (float*)d_out;

    float  *pWcE, *pWAB, *pWdt, *pAB1, *pH;
    __half *pAB2h, *pZh;
    cudaGetSymbolAddress((void**)&pWcE,  g_Wc_enc);
    cudaGetSymbolAddress((void**)&pWAB,  g_W_AB);
    cudaGetSymbolAddress((void**)&pWdt,  g_Wdt);
    cudaGetSymbolAddress((void**)&pAB1,  g_AB1);
    cudaGetSymbolAddress((void**)&pH,    g_h);
    cudaGetSymbolAddress((void**)&pAB2h, g_AB2h);
    cudaGetSymbolAddress((void**)&pZh,   g_zh);

    cudaFuncSetAttribute((const void*)gemm_cl<2, false>,
                         cudaFuncAttributeMaxDynamicSharedMemorySize, GEMM_SMEM);
    cudaFuncSetAttribute((const void*)gemm_cl<8, true>,
                         cudaFuncAttributeMaxDynamicSharedMemorySize, GEMM_SMEM);

    // 1. combined weights (tf32, shuffle-permuted)
    prep_weights<<<308, 256>>>(We, Wm, Wlv, Wd, bm, blv);
    // 2. AB1 = x @ [Wd_enc | Wb_enc]   (50000 x 128)
    gemm_cl<2, false><<<dim3(391, 1), 256, GEMM_SMEM>>>(x, pWcE, pAB1, N_NODES, 128, nullptr);
    // 3. h = leaky(A + max_k B[src] + b)   (tf32-rounded)
    gather_enc<<<12500, 256>>>(src, be);
    // 4. AB2 = h @ [Am'|Alv'|Bm'|Blv']  (50000 x 1024, fp16 out)
    gemm_cl<8, true><<<dim3(391, 2), 256, GEMM_SMEM>>>(pH, pWAB, pAB2h, N_NODES, 1024, nullptr);
    // 5. gather-max x2 + reparametrize -> z (fp16, contiguous)
    gather_ml<<<N_NODES, 256>>>(src, noise);
    // 6. out = z @ W_dec + b_dec
    gemm_dec<<<NT_DEC, 256>>>(pZh, pWdt, out, bd);
}

// round 11
// speedup vs baseline: 1.3109x; 1.1173x over previous
#include <cuda_runtime.h>
#include <cuda_fp16.h>
#include <math.h>

#define N_NODES 50000
#define N_PAD   50048    // padded to 128-row tiles
#define KNN     8
#define NR      200000   // N * R
#define NT_DEC  1563     // ceil(NR/128)

// ---------------- scratch (device globals) ----------------
// All weights fp16, n-major [n][64k] so B-fragments load contiguously.
__device__ __half g_WcE_h[128 * 64];                 // [n][k]: n<64 own(A), n>=64 neighbor(B)
__device__ __half g_WAB_h[1024 * 64];                // [n][k], shuffle-permuted
__device__ __half g_Wdt_h[64 * 64];                  // [n][k] decoder
__device__ float  g_bmp [256];                       // permuted biases
__device__ float  g_blvp[256];
__device__ __half g_AB1h[(size_t)N_NODES * 128];     // [node][ own(64) | nb(64) ]
__device__ __half g_hh  [(size_t)N_PAD * 64];        // fp16 h, zero-padded rows
__device__ __half g_AB2h[(size_t)N_NODES * 1024];    // [ own(512) | neighbor(512) ]
__device__ __half g_zh  [(size_t)NT_DEC * 128 * 64]; // fp16 z, padded to full tiles

// ---------------- weight prep (fp16, n-major, shuffle-permuted) ----------------
// concat([xi, xj-xi]) @ W == xi @ (W_top - W_bot) + xj @ W_bot
// sigma(p)=(p&63)*4+(p>>6) bakes point_shuffle into mean/logvar columns.
__global__ void prep_weights(const float* __restrict__ We,
                             const float* __restrict__ Wm,
                             const float* __restrict__ Wlv,
                             const float* __restrict__ Wd,
                             const float* __restrict__ bm,
                             const float* __restrict__ blv) {
    int idx = blockIdx.x * blockDim.x + threadIdx.x;
    if (idx < 128 * 64) {                            // encoder: [n][k]
        int n = idx >> 6, k = idx & 63;
        float v = (n < 64) ? We[k * 64 + n] - We[(64 + k) * 64 + n]
                           : We[(64 + k) * 64 + (n - 64)];
        g_WcE_h[idx] = __float2half_rn(v);
    }
    int i2 = idx - 128 * 64;
    if (i2 >= 0 && i2 < 1024 * 64) {                 // mean/logvar: [n][k]
        int n = i2 >> 6, k = i2 & 63;
        int half = n >> 9;                           // 0 = own(A), 1 = neighbor(B)
        int cc   = n & 511;
        const float* Wsrc = (cc < 256) ? Wm : Wlv;
        int j  = cc & 255;
        int ch = ((j & 63) << 2) | (j >> 6);         // sigma
        float v;
        if (half == 0) v = Wsrc[k * 256 + ch] - Wsrc[(64 + k) * 256 + ch];
        else           v = Wsrc[(64 + k) * 256 + ch];
        g_WAB_h[i2] = __float2half_rn(v);
    }
    int i3 = idx - 128 * 64 - 1024 * 64;
    if (i3 >= 0 && i3 < 64 * 64) {                   // decoder transpose: [n][k]
        int n = i3 >> 6, k = i3 & 63;
        g_Wdt_h[i3] = __float2half_rn(Wd[k * 64 + n]);
    }
    int i4 = idx - 128 * 64 - 1024 * 64 - 64 * 64;
    if (i4 >= 0 && i4 < 512) {
        int p = i4 & 255;
        int ch = ((p & 63) << 2) | (p >> 6);
        if (i4 < 256) g_bmp[p]  = bm[ch];
        else          g_blvp[p] = blv[ch];
    }
}

// ---------------- fp16 tensor-core GEMM (m16n8k16), cp.async pipelined ---------
// C[M,Nout] = X[M,64] @ Wt^T (+bias), Wt stored n-major [Nout][64] fp16.
// 128 rows x (NT*64) cols per block, 8 warps, 32x32 warp tiles.
#define XSH 72   // halves per X row  (banks qr*4+qc: conflict-free)
#define KSH 72   // halves per Wt row

__device__ __forceinline__ void cp16(unsigned dst, const void* src) {
    asm volatile("cp.async.ca.shared.global [%0], [%1], 16;" :: "r"(dst), "l"(src));
}

template<int NT, bool HALF_IN, bool HALF_OUT>
__global__ void __launch_bounds__(256, 2)
gemm16(const void* __restrict__ Xv, const __half* __restrict__ Wt,
       void* __restrict__ Cv, int M, int Nout, const float* __restrict__ bias)
{
    __shared__ __half xsh[128 * XSH];
    __shared__ __half wtb[2][64 * KSH];
    const unsigned xu = (unsigned)__cvta_generic_to_shared(xsh);
    const unsigned wu[2] = { (unsigned)__cvta_generic_to_shared(wtb[0]),
                             (unsigned)__cvta_generic_to_shared(wtb[1]) };

    const int tid  = threadIdx.x;
    const int row0 = blockIdx.x * 128;

    if (HALF_IN) {   // input padded to full tiles -> raw async copy
        const __half* Xh = (const __half*)Xv;
        #pragma unroll
        for (int i = 0; i < 4; i++) {
            int f = tid + i * 256, r = f >> 3, c8 = (f & 7) * 8;
            cp16(xu + (unsigned)(r * XSH + c8) * 2,
                 Xh + (size_t)row0 * 64 + r * 64 + c8);
        }
        asm volatile("cp.async.commit_group;");
    }
    {   // prefetch W tile 0 (rows col0..col0+63 of n-major Wt)
        const int col0 = blockIdx.y * NT * 64;
        #pragma unroll
        for (int i = 0; i < 2; i++) {
            int f = tid + i * 256, r = f >> 3, c8 = (f & 7) * 8;
            cp16(wu[0] + (unsigned)(r * KSH + c8) * 2,
                 Wt + (size_t)(col0 + r) * 64 + c8);
        }
        asm volatile("cp.async.commit_group;");
    }
    if (!HALF_IN) {  // fp32 input: load + convert (guarded)
        const float* Xf = (const float*)Xv;
        #pragma unroll
        for (int i = 0; i < 8; i++) {
            int f = tid + i * 256, r = f >> 4, c4 = (f & 15) * 4;
            float4 v = make_float4(0.f, 0.f, 0.f, 0.f);
            if (row0 + r < M) v = *(const float4*)(Xf + (size_t)(row0 + r) * 64 + c4);
            *(__half2*)(xsh + r * XSH + c4)     = __floats2half2_rn(v.x, v.y);
            *(__half2*)(xsh + r * XSH + c4 + 2) = __floats2half2_rn(v.z, v.w);
        }
    } else {
        asm volatile("cp.async.wait_group 1;");   // X group retired
    }
    __syncthreads();

    const int warp = tid >> 5, lane = tid & 31;
    const int wr = warp >> 1, wc = warp & 1;
    const int qr = lane >> 2, qc = lane & 3;

    // hoist A-fragments (K=64 -> 4 k-blocks of 16) into 32 registers
    unsigned areg[4][2][4];
    #pragma unroll
    for (int kb = 0; kb < 4; kb++)
        #pragma unroll
        for (int mi = 0; mi < 2; mi++) {
            const __half* p = xsh + (wr * 32 + mi * 16 + qr) * XSH + kb * 16 + qc * 2;
            areg[kb][mi][0] = *(const unsigned*)(p);
            areg[kb][mi][1] = *(const unsigned*)(p + 8 * XSH);
            areg[kb][mi][2] = *(const unsigned*)(p + 8);
            areg[kb][mi][3] = *(const unsigned*)(p + 8 * XSH + 8);
        }

    for (int t = 0; t < NT; t++) {
        if (t + 1 < NT) {
            const int coln = (blockIdx.y * NT + t + 1) * 64;
            unsigned wd = wu[(t + 1) & 1];
            #pragma unroll
            for (int i = 0; i < 2; i++) {
                int f = tid + i * 256, r = f >> 3, c8 = (f & 7) * 8;
                cp16(wd + (unsigned)(r * KSH + c8) * 2,
                     Wt + (size_t)(coln + r) * 64 + c8);
            }
            asm volatile("cp.async.commit_group;");
            asm volatile("cp.async.wait_group 1;");
        } else {
            asm volatile("cp.async.wait_group 0;");
        }
        __syncthreads();

        const __half* wt = wtb[t & 1];
        float acc[2][4][4];
        #pragma unroll
        for (int mi = 0; mi < 2; mi++)
            #pragma unroll
            for (int ni = 0; ni < 4; ni++)
                #pragma unroll
                for (int s = 0; s < 4; s++) acc[mi][ni][s] = 0.f;

        #pragma unroll
        for (int kb = 0; kb < 4; kb++) {
            unsigned b[4][2];
            #pragma unroll
            for (int ni = 0; ni < 4; ni++) {
                const __half* p = wt + (wc * 32 + ni * 8 + qr) * KSH + kb * 16 + qc * 2;
                b[ni][0] = *(const unsigned*)(p);
                b[ni][1] = *(const unsigned*)(p + 8);
            }
            #pragma unroll
            for (int mi = 0; mi < 2; mi++)
                #pragma unroll
                for (int ni = 0; ni < 4; ni++)
                    asm volatile(
                        "mma.sync.aligned.m16n8k16.row.col.f32.f16.f16.f32 "
                        "{%0,%1,%2,%3}, {%4,%5,%6,%7}, {%8,%9}, {%0,%1,%2,%3};"
                        : "+f"(acc[mi][ni][0]), "+f"(acc[mi][ni][1]),
                          "+f"(acc[mi][ni][2]), "+f"(acc[mi][ni][3])
                        : "r"(areg[kb][mi][0]), "r"(areg[kb][mi][1]),
                          "r"(areg[kb][mi][2]), "r"(areg[kb][mi][3]),
                          "r"(b[ni][0]), "r"(b[ni][1]));
        }
        __syncthreads();

        const int col0 = (blockIdx.y * NT + t) * 64;
        #pragma unroll
        for (int mi = 0; mi < 2; mi++)
            #pragma unroll
            for (int half = 0; half < 2; half++) {
                int row = row0 + wr * 32 + mi * 16 + qr + half * 8;
                if (row < M) {
                    #pragma unroll
                    for (int ni = 0; ni < 4; ni++) {
                        int col = col0 + wc * 32 + ni * 8 + qc * 2;
                        float vx = acc[mi][ni][half * 2 + 0];
                        float vy = acc[mi][ni][half * 2 + 1];
                        if (bias) {
                            float2 bv = *(const float2*)(bias + col);
                            vx += bv.x; vy += bv.y;
                        }
                        if (HALF_OUT) {
                            *(__half2*)((__half*)Cv + (size_t)row * Nout + col) =
                                __floats2half2_rn(vx, vy);
                        } else {
                            *(float2*)((float*)Cv + (size_t)row * Nout + col) =
                                make_float2(vx, vy);
                        }
                    }
                }
            }
    }
}

// ---------------- encoder gather-max + bias + leaky_relu(0.2) ----------------
__global__ void __launch_bounds__(256)
gather_enc(const int* __restrict__ src, const float* __restrict__ b) {
    __shared__ int ss[32];
    int tid = threadIdx.x;
    if (tid < 32) ss[tid] = src[blockIdx.x * 32 + tid];
    __syncthreads();
    int local = tid >> 6;
    int j     = tid & 63;
    int node  = blockIdx.x * 4 + local;
    float a = __half2float(__ldcs(g_AB1h + (size_t)node * 128 + j));
    float m = -3.4e38f;
    #pragma unroll
    for (int k = 0; k < KNN; k++) {
        int s = ss[local * 8 + k];
        m = fmaxf(m, __half2float(g_AB1h[(size_t)s * 128 + 64 + j]));
    }
    float v = a + m + b[j];
    v = v > 0.f ? v : 0.2f * v;
    g_hh[(size_t)node * 64 + j] = __float2half_rn(v);
}

// ---------------- mean/logvar gather-max + reparametrize (pre-shuffled) --------
__global__ void __launch_bounds__(256)
gather_ml(const int* __restrict__ src, const float* __restrict__ noise) {
    __shared__ int ss[KNN];
    int tid  = threadIdx.x;
    int node = blockIdx.x;
    if (tid < KNN) ss[tid] = src[node * KNN + tid];
    __syncthreads();
    size_t abase = (size_t)node * 1024;
    float am  = __half2float(__ldcs(g_AB2h + abase + tid));
    float alv = __half2float(__ldcs(g_AB2h + abase + 256 + tid));
    float mm = -3.4e38f, mlv = -3.4e38f;
    #pragma unroll
    for (int k = 0; k < KNN; k++) {
        size_t sb = (size_t)ss[k] * 1024 + 512;
        mm  = fmaxf(mm,  __half2float(g_AB2h[sb + tid]));
        mlv = fmaxf(mlv, __half2float(g_AB2h[sb + 256 + tid]));
    }
    float zm  = am  + mm  + g_bmp[tid];
    float zlv = alv + mlv + g_blvp[tid];
    size_t o = (size_t)node * 256 + tid;
    float nz = __ldcs(noise + o);
    g_zh[o] = __float2half_rn(fmaf(nz, expf(0.5f * zlv), zm));
}

// ---------------- launch ----------------
extern "C" void kernel_launch(void* const* d_in, const int* in_sizes, int n_in,
                              void* d_out, int out_size) {
    const float* x     = (const float*)d_in[0];
    const int*   src   = (const int*)  d_in[1];
    const float* noise = (const float*)d_in[3];
    const float* We    = (const float*)d_in[4];
    const float* be    = (const float*)d_in[5];
    const float* Wm    = (const float*)d_in[6];
    const float* bm    = (const float*)d_in[7];
    const float* Wlv   = (const float*)d_in[8];
    const float* blv   = (const float*)d_in[9];
    const float* Wd    = (const float*)d_in[10];
    const float* bd    = (const float*)d_in[11];
    float* out = (float*)d_out;

    __half *pWcE, *pWAB, *pWdt, *pAB1, *pH, *pAB2, *pZ;
    cudaGetSymbolAddress((void**)&pWcE, g_WcE_h);
    cudaGetSymbolAddress((void**)&pWAB, g_WAB_h);
    cudaGetSymbolAddress((void**)&pWdt, g_Wdt_h);
    cudaGetSymbolAddress((void**)&pAB1, g_AB1h);
    cudaGetSymbolAddress((void**)&pH,   g_hh);
    cudaGetSymbolAddress((void**)&pAB2, g_AB2h);
    cudaGetSymbolAddress((void**)&pZ,   g_zh);

    // 1. combined weights (fp16, n-major, shuffle-permuted)
    prep_weights<<<307, 256>>>(We, Wm, Wlv, Wd, bm, blv);
    // 2. AB1 = x @ [A_enc | B_enc]   (50000 x 128, fp16 out)
    gemm16<2, false, true><<<dim3(391, 1), 256>>>(x, pWcE, pAB1, N_NODES, 128, nullptr);
    // 3. h = leaky(A + max_k B[src] + b)   (fp16)
    gather_enc<<<12500, 256>>>(src, be);
    // 4. AB2 = h @ [Am'|Alv'|Bm'|Blv']  (50000 x 1024, fp16)
    gemm16<8, true, true><<<dim3(391, 2), 256>>>(pH, pWAB, pAB2, N_NODES, 1024, nullptr);
    // 5. gather-max x2 + reparametrize -> z (fp16, contiguous)
    gather_ml<<<N_NODES, 256>>>(src, noise);
    // 6. out = z @ W_dec + b_dec
    gemm16<1, true, false><<<dim3(NT_DEC, 1), 256>>>(pZ, pWdt, out, NR, 64, bd);
}

// round 12
// speedup vs baseline: 1.3401x; 1.0223x over previous
#include <cuda_runtime.h>
#include <cuda_fp16.h>
#include <math.h>

#define N_NODES 50000
#define N_PAD   50048    // padded to 64-row tiles (782*64)
#define KNN     8
#define NR      200000   // N * R = 3125 * 64 exactly

// ---------------- scratch (device globals) ----------------
// All weights fp16, n-major [n][64k] so B-fragments load contiguously.
__device__ __half g_WcE_h[128 * 64];                 // [n][k]: n<64 own(A), n>=64 neighbor(B)
__device__ __half g_WAB_h[1024 * 64];                // [n][k], shuffle-permuted
__device__ __half g_Wdt_h[64 * 64];                  // [n][k] decoder
__device__ float  g_bmp [256];                       // permuted biases
__device__ float  g_blvp[256];
__device__ __half g_AB1h[(size_t)N_NODES * 128];     // [node][ own(64) | nb(64) ]
__device__ __half g_hh  [(size_t)N_PAD * 64];        // fp16 h, zero-padded rows
__device__ __half g_AB2h[(size_t)N_NODES * 1024];    // [ own(512) | neighbor(512) ]
__device__ __half g_zh  [(size_t)NR * 64];           // fp16 z, shuffle-contiguous

// ---------------- weight prep (fp16, n-major, shuffle-permuted) ----------------
// concat([xi, xj-xi]) @ W == xi @ (W_top - W_bot) + xj @ W_bot
// sigma(p)=(p&63)*4+(p>>6) bakes point_shuffle into mean/logvar columns.
__global__ void prep_weights(const float* __restrict__ We,
                             const float* __restrict__ Wm,
                             const float* __restrict__ Wlv,
                             const float* __restrict__ Wd,
                             const float* __restrict__ bm,
                             const float* __restrict__ blv) {
    int idx = blockIdx.x * blockDim.x + threadIdx.x;
    if (idx < 128 * 64) {                            // encoder: [n][k]
        int n = idx >> 6, k = idx & 63;
        float v = (n < 64) ? We[k * 64 + n] - We[(64 + k) * 64 + n]
                           : We[(64 + k) * 64 + (n - 64)];
        g_WcE_h[idx] = __float2half_rn(v);
    }
    int i2 = idx - 128 * 64;
    if (i2 >= 0 && i2 < 1024 * 64) {                 // mean/logvar: [n][k]
        int n = i2 >> 6, k = i2 & 63;
        int half = n >> 9;                           // 0 = own(A), 1 = neighbor(B)
        int cc   = n & 511;
        const float* Wsrc = (cc < 256) ? Wm : Wlv;
        int j  = cc & 255;
        int ch = ((j & 63) << 2) | (j >> 6);         // sigma
        float v;
        if (half == 0) v = Wsrc[k * 256 + ch] - Wsrc[(64 + k) * 256 + ch];
        else           v = Wsrc[(64 + k) * 256 + ch];
        g_WAB_h[i2] = __float2half_rn(v);
    }
    int i3 = idx - 128 * 64 - 1024 * 64;
    if (i3 >= 0 && i3 < 64 * 64) {                   // decoder transpose: [n][k]
        int n = i3 >> 6, k = i3 & 63;
        g_Wdt_h[i3] = __float2half_rn(Wd[k * 64 + n]);
    }
    int i4 = idx - 128 * 64 - 1024 * 64 - 64 * 64;
    if (i4 >= 0 && i4 < 512) {
        int p = i4 & 255;
        int ch = ((p & 63) << 2) | (p >> 6);
        if (i4 < 256) g_bmp[p]  = bm[ch];
        else          g_blvp[p] = blv[ch];
    }
}

// ---------------- fp16 tensor-core GEMM (m16n8k16), 128-thread CTAs -----------
// C[M,Nout] = X[M,64] @ Wt^T (+bias), Wt n-major [Nout][64] fp16.
// 64 rows x (NT*64) cols per block, 4 warps (2x2), 32x32 warp tiles.
// 27.6 KB smem, ~110 regs -> 4 CTAs/SM for cross-CTA latency hiding.
#define XSH 72   // halves per X row  (bank = 4*qr+qc: conflict-free frags)
#define KSH 72   // halves per Wt row

__device__ __forceinline__ void cp16(unsigned dst, const void* src) {
    asm volatile("cp.async.ca.shared.global [%0], [%1], 16;" :: "r"(dst), "l"(src));
}

template<int NT, bool HALF_IN, bool HALF_OUT>
__global__ void __launch_bounds__(128, 4)
gemm16(const void* __restrict__ Xv, const __half* __restrict__ Wt,
       void* __restrict__ Cv, int M, int Nout, const float* __restrict__ bias)
{
    __shared__ __half xsh[64 * XSH];
    __shared__ __half wtb[2][64 * KSH];
    const unsigned xu = (unsigned)__cvta_generic_to_shared(xsh);
    const unsigned wu[2] = { (unsigned)__cvta_generic_to_shared(wtb[0]),
                             (unsigned)__cvta_generic_to_shared(wtb[1]) };

    const int tid  = threadIdx.x;
    const int row0 = blockIdx.x * 64;

    if (HALF_IN) {   // input padded to full 64-row tiles -> raw async copy
        const __half* Xh = (const __half*)Xv;
        #pragma unroll
        for (int i = 0; i < 4; i++) {
            int f = tid + i * 128, r = f >> 3, c8 = (f & 7) * 8;
            cp16(xu + (unsigned)(r * XSH + c8) * 2,
                 Xh + (size_t)row0 * 64 + r * 64 + c8);
        }
        asm volatile("cp.async.commit_group;");
    }
    {   // prefetch W tile 0 (rows col0..col0+63 of n-major Wt)
        const int col0 = blockIdx.y * NT * 64;
        #pragma unroll
        for (int i = 0; i < 4; i++) {
            int f = tid + i * 128, r = f >> 3, c8 = (f & 7) * 8;
            cp16(wu[0] + (unsigned)(r * KSH + c8) * 2,
                 Wt + (size_t)(col0 + r) * 64 + c8);
        }
        asm volatile("cp.async.commit_group;");
    }
    if (!HALF_IN) {  // fp32 input: load + convert (row-guarded)
        const float* Xf = (const float*)Xv;
        #pragma unroll
        for (int i = 0; i < 8; i++) {
            int f = tid + i * 128, r = f >> 4, c4 = (f & 15) * 4;
            float4 v = make_float4(0.f, 0.f, 0.f, 0.f);
            if (row0 + r < M) v = *(const float4*)(Xf + (size_t)(row0 + r) * 64 + c4);
            *(__half2*)(xsh + r * XSH + c4)     = __floats2half2_rn(v.x, v.y);
            *(__half2*)(xsh + r * XSH + c4 + 2) = __floats2half2_rn(v.z, v.w);
        }
    } else {
        asm volatile("cp.async.wait_group 1;");   // X group retired
    }
    __syncthreads();

    const int warp = tid >> 5, lane = tid & 31;
    const int wr = warp >> 1, wc = warp & 1;     // 2x2 warp grid
    const int qr = lane >> 2, qc = lane & 3;

    // hoist A-fragments (K=64 -> 4 k-blocks of 16) into 32 registers
    unsigned areg[4][2][4];
    #pragma unroll
    for (int kb = 0; kb < 4; kb++)
        #pragma unroll
        for (int mi = 0; mi < 2; mi++) {
            const __half* p = xsh + (wr * 32 + mi * 16 + qr) * XSH + kb * 16 + qc * 2;
            areg[kb][mi][0] = *(const unsigned*)(p);
            areg[kb][mi][1] = *(const unsigned*)(p + 8 * XSH);
            areg[kb][mi][2] = *(const unsigned*)(p + 8);
            areg[kb][mi][3] = *(const unsigned*)(p + 8 * XSH + 8);
        }

    for (int t = 0; t < NT; t++) {
        if (t + 1 < NT) {
            const int coln = (blockIdx.y * NT + t + 1) * 64;
            unsigned wd = wu[(t + 1) & 1];
            #pragma unroll
            for (int i = 0; i < 4; i++) {
                int f = tid + i * 128, r = f >> 3, c8 = (f & 7) * 8;
                cp16(wd + (unsigned)(r * KSH + c8) * 2,
                     Wt + (size_t)(coln + r) * 64 + c8);
            }
            asm volatile("cp.async.commit_group;");
            asm volatile("cp.async.wait_group 1;");
        } else {
            asm volatile("cp.async.wait_group 0;");
        }
        __syncthreads();

        const __half* wt = wtb[t & 1];
        float acc[2][4][4];
        #pragma unroll
        for (int mi = 0; mi < 2; mi++)
            #pragma unroll
            for (int ni = 0; ni < 4; ni++)
                #pragma unroll
                for (int s = 0; s < 4; s++) acc[mi][ni][s] = 0.f;

        #pragma unroll
        for (int kb = 0; kb < 4; kb++) {
            unsigned b[4][2];
            #pragma unroll
            for (int ni = 0; ni < 4; ni++) {
                const __half* p = wt + (wc * 32 + ni * 8 + qr) * KSH + kb * 16 + qc * 2;
                b[ni][0] = *(const unsigned*)(p);
                b[ni][1] = *(const unsigned*)(p + 8);
            }
            #pragma unroll
            for (int mi = 0; mi < 2; mi++)
                #pragma unroll
                for (int ni = 0; ni < 4; ni++)
                    asm volatile(
                        "mma.sync.aligned.m16n8k16.row.col.f32.f16.f16.f32 "
                        "{%0,%1,%2,%3}, {%4,%5,%6,%7}, {%8,%9}, {%0,%1,%2,%3};"
                        : "+f"(acc[mi][ni][0]), "+f"(acc[mi][ni][1]),
                          "+f"(acc[mi][ni][2]), "+f"(acc[mi][ni][3])
                        : "r"(areg[kb][mi][0]), "r"(areg[kb][mi][1]),
                          "r"(areg[kb][mi][2]), "r"(areg[kb][mi][3]),
                          "r"(b[ni][0]), "r"(b[ni][1]));
        }
        __syncthreads();

        const int col0 = (blockIdx.y * NT + t) * 64;
        #pragma unroll
        for (int mi = 0; mi < 2; mi++)
            #pragma unroll
            for (int half = 0; half < 2; half++) {
                int row = row0 + wr * 32 + mi * 16 + qr + half * 8;
                if (row < M) {
                    #pragma unroll
                    for (int ni = 0; ni < 4; ni++) {
                        int col = col0 + wc * 32 + ni * 8 + qc * 2;
                        float vx = acc[mi][ni][half * 2 + 0];
                        float vy = acc[mi][ni][half * 2 + 1];
                        if (bias) {
                            float2 bv = *(const float2*)(bias + col);
                            vx += bv.x; vy += bv.y;
                        }
                        if (HALF_OUT) {
                            *(__half2*)((__half*)Cv + (size_t)row * Nout + col) =
                                __floats2half2_rn(vx, vy);
                        } else {
                            *(float2*)((float*)Cv + (size_t)row * Nout + col) =
                                make_float2(vx, vy);
                        }
                    }
                }
            }
    }
}

// ---------------- encoder gather-max + bias + leaky_relu(0.2) ----------------
__global__ void __launch_bounds__(256)
gather_enc(const int* __restrict__ src, const float* __restrict__ b) {
    __shared__ int ss[32];
    int tid = threadIdx.x;
    if (tid < 32) ss[tid] = src[blockIdx.x * 32 + tid];
    __syncthreads();
    int local = tid >> 6;
    int j     = tid & 63;
    int node  = blockIdx.x * 4 + local;
    float a = __half2float(__ldcs(g_AB1h + (size_t)node * 128 + j));
    float m = -3.4e38f;
    #pragma unroll
    for (int k = 0; k < KNN; k++) {
        int s = ss[local * 8 + k];
        m = fmaxf(m, __half2float(g_AB1h[(size_t)s * 128 + 64 + j]));
    }
    float v = a + m + b[j];
    v = v > 0.f ? v : 0.2f * v;
    g_hh[(size_t)node * 64 + j] = __float2half_rn(v);
}

// ---------------- mean/logvar gather-max + reparametrize (pre-shuffled) --------
__global__ void __launch_bounds__(256)
gather_ml(const int* __restrict__ src, const float* __restrict__ noise) {
    __shared__ int ss[KNN];
    int tid  = threadIdx.x;
    int node = blockIdx.x;
    if (tid < KNN) ss[tid] = src[node * KNN + tid];
    __syncthreads();
    size_t abase = (size_t)node * 1024;
    float am  = __half2float(__ldcs(g_AB2h + abase + tid));
    float alv = __half2float(__ldcs(g_AB2h + abase + 256 + tid));
    float mm = -3.4e38f, mlv = -3.4e38f;
    #pragma unroll
    for (int k = 0; k < KNN; k++) {
        size_t sb = (size_t)ss[k] * 1024 + 512;
        mm  = fmaxf(mm,  __half2float(g_AB2h[sb + tid]));
        mlv = fmaxf(mlv, __half2float(g_AB2h[sb + 256 + tid]));
    }
    float zm  = am  + mm  + g_bmp[tid];
    float zlv = alv + mlv + g_blvp[tid];
    size_t o = (size_t)node * 256 + tid;
    float nz = __ldcs(noise + o);
    g_zh[o] = __float2half_rn(fmaf(nz, expf(0.5f * zlv), zm));
}

// ---------------- launch ----------------
extern "C" void kernel_launch(void* const* d_in, const int* in_sizes, int n_in,
                              void* d_out, int out_size) {
    const float* x     = (const float*)d_in[0];
    const int*   src   = (const int*)  d_in[1];
    const float* noise = (const float*)d_in[3];
    const float* We    = (const float*)d_in[4];
    const float* be    = (const float*)d_in[5];
    const float* Wm    = (const float*)d_in[6];
    const float* bm    = (const float*)d_in[7];
    const float* Wlv   = (const float*)d_in[8];
    const float* blv   = (const float*)d_in[9];
    const float* Wd    = (const float*)d_in[10];
    const float* bd    = (const float*)d_in[11];
    float* out = (float*)d_out;

    __half *pWcE, *pWAB, *pWdt, *pAB1, *pH, *pAB2, *pZ;
    cudaGetSymbolAddress((void**)&pWcE, g_WcE_h);
    cudaGetSymbolAddress((void**)&pWAB, g_WAB_h);
    cudaGetSymbolAddress((void**)&pWdt, g_Wdt_h);
    cudaGetSymbolAddress((void**)&pAB1, g_AB1h);
    cudaGetSymbolAddress((void**)&pH,   g_hh);
    cudaGetSymbolAddress((void**)&pAB2, g_AB2h);
    cudaGetSymbolAddress((void**)&pZ,   g_zh);

    // 1. combined weights (fp16, n-major, shuffle-permuted)
    prep_weights<<<307, 256>>>(We, Wm, Wlv, Wd, bm, blv);
    // 2. AB1 = x @ [A_enc | B_enc]   (50000 x 128, fp16 out)
    gemm16<2, false, true><<<dim3(782, 1), 128>>>(x, pWcE, pAB1, N_NODES, 128, nullptr);
    // 3. h = leaky(A + max_k B[src] + b)   (fp16)
    gather_enc<<<12500, 256>>>(src, be);
    // 4. AB2 = h @ [Am'|Alv'|Bm'|Blv']  (50000 x 1024, fp16)
    gemm16<8, true, true><<<dim3(782, 2), 128>>>(pH, pWAB, pAB2, N_NODES, 1024, nullptr);
    // 5. gather-max x2 + reparametrize -> z (fp16, contiguous)
    gather_ml<<<N_NODES, 256>>>(src, noise);
    // 6. out = z @ W_dec + b_dec   (NR = 3125 * 64 exactly, no padding)
    gemm16<1, true, false><<<dim3(3125, 1), 128>>>(pZ, pWdt, out, NR, 64, bd);
}

// round 13
// speedup vs baseline: 1.3831x; 1.0321x over previous
#include <cuda_runtime.h>
#include <cuda_fp16.h>
#include <math.h>

#define N_NODES 50000
#define N_PAD   50048    // padded to 128-row tiles (391*128)
#define KNN     8
#define NR      200000   // N * R
#define NT_DEC  1563     // ceil(NR/128)

// ---------------- scratch (device globals) ----------------
// All weights fp16, n-major [n][64k] so B-fragments load contiguously.
__device__ __half g_WcE_h[128 * 64];                 // [n][k]: n<64 own(A), n>=64 neighbor(B)
__device__ __half g_WAB_h[1024 * 64];                // [n][k], shuffle-permuted
__device__ __half g_Wdt_h[64 * 64];                  // [n][k] decoder
__device__ float  g_bmp [256];                       // permuted biases
__device__ float  g_blvp[256];
__device__ __half g_AB1h[(size_t)N_NODES * 128];     // [node][ own(64) | nb(64) ]
__device__ __half g_hh  [(size_t)N_PAD * 64];        // fp16 h, zero-padded rows
__device__ __half g_AB2h[(size_t)N_NODES * 1024];    // [ own(512) | neighbor(512) ]
__device__ __half g_zh  [(size_t)NT_DEC * 128 * 64]; // fp16 z, padded to full tiles

// ---------------- weight prep (fp16, n-major, shuffle-permuted) ----------------
// concat([xi, xj-xi]) @ W == xi @ (W_top - W_bot) + xj @ W_bot
// sigma(p)=(p&63)*4+(p>>6) bakes point_shuffle into mean/logvar columns.
__global__ void prep_weights(const float* __restrict__ We,
                             const float* __restrict__ Wm,
                             const float* __restrict__ Wlv,
                             const float* __restrict__ Wd,
                             const float* __restrict__ bm,
                             const float* __restrict__ blv) {
    int idx = blockIdx.x * blockDim.x + threadIdx.x;
    if (idx < 128 * 64) {                            // encoder: [n][k]
        int n = idx >> 6, k = idx & 63;
        float v = (n < 64) ? We[k * 64 + n] - We[(64 + k) * 64 + n]
                           : We[(64 + k) * 64 + (n - 64)];
        g_WcE_h[idx] = __float2half_rn(v);
    }
    int i2 = idx - 128 * 64;
    if (i2 >= 0 && i2 < 1024 * 64) {                 // mean/logvar: [n][k]
        int n = i2 >> 6, k = i2 & 63;
        int half = n >> 9;                           // 0 = own(A), 1 = neighbor(B)
        int cc   = n & 511;
        const float* Wsrc = (cc < 256) ? Wm : Wlv;
        int j  = cc & 255;
        int ch = ((j & 63) << 2) | (j >> 6);         // sigma
        float v;
        if (half == 0) v = Wsrc[k * 256 + ch] - Wsrc[(64 + k) * 256 + ch];
        else           v = Wsrc[(64 + k) * 256 + ch];
        g_WAB_h[i2] = __float2half_rn(v);
    }
    int i3 = idx - 128 * 64 - 1024 * 64;
    if (i3 >= 0 && i3 < 64 * 64) {                   // decoder transpose: [n][k]
        int n = i3 >> 6, k = i3 & 63;
        g_Wdt_h[i3] = __float2half_rn(Wd[k * 64 + n]);
    }
    int i4 = idx - 128 * 64 - 1024 * 64 - 64 * 64;
    if (i4 >= 0 && i4 < 512) {
        int p = i4 & 255;
        int ch = ((p & 63) << 2) | (p >> 6);
        if (i4 < 256) g_bmp[p]  = bm[ch];
        else          g_blvp[p] = blv[ch];
    }
}

// ---------------- fp16 tensor-core GEMM (m16n8k16), 64x32 warp tiles ----------
// C[M,Nout] = X[M,64] @ Wt^T (+bias), Wt n-major [Nout][64] fp16.
// 128 rows x (NT*64) cols per block, 4 warps (2x2), 64x32 per warp.
// Doubled M_warp halves b-frag LDS per FLOP; 128-row blocks halve W restaging.
#define XSH 72   // halves per X row  (bank = 4*qr+qc: conflict-free frags)
#define KSH 72   // halves per Wt row

__device__ __forceinline__ void cp16(unsigned dst, const void* src) {
    asm volatile("cp.async.ca.shared.global [%0], [%1], 16;" :: "r"(dst), "l"(src));
}

template<int NT, bool HALF_IN, bool HALF_OUT>
__global__ void __launch_bounds__(128, 3)
gemm16(const void* __restrict__ Xv, const __half* __restrict__ Wt,
       void* __restrict__ Cv, int M, int Nout, const float* __restrict__ bias)
{
    __shared__ __half xsh[128 * XSH];
    __shared__ __half wtb[2][64 * KSH];
    const unsigned xu = (unsigned)__cvta_generic_to_shared(xsh);
    const unsigned wu[2] = { (unsigned)__cvta_generic_to_shared(wtb[0]),
                             (unsigned)__cvta_generic_to_shared(wtb[1]) };

    const int tid  = threadIdx.x;
    const int row0 = blockIdx.x * 128;

    if (HALF_IN) {   // input padded to full 128-row tiles -> raw async copy
        const __half* Xh = (const __half*)Xv;
        #pragma unroll
        for (int i = 0; i < 8; i++) {
            int f = tid + i * 128, r = f >> 3, c8 = (f & 7) * 8;
            cp16(xu + (unsigned)(r * XSH + c8) * 2,
                 Xh + (size_t)row0 * 64 + r * 64 + c8);
        }
        asm volatile("cp.async.commit_group;");
    }
    {   // prefetch W tile 0 (rows col0..col0+63 of n-major Wt)
        const int col0 = blockIdx.y * NT * 64;
        #pragma unroll
        for (int i = 0; i < 4; i++) {
            int f = tid + i * 128, r = f >> 3, c8 = (f & 7) * 8;
            cp16(wu[0] + (unsigned)(r * KSH + c8) * 2,
                 Wt + (size_t)(col0 + r) * 64 + c8);
        }
        asm volatile("cp.async.commit_group;");
    }
    if (!HALF_IN) {  // fp32 input: load + convert (row-guarded)
        const float* Xf = (const float*)Xv;
        #pragma unroll
        for (int i = 0; i < 16; i++) {
            int f = tid + i * 128, r = f >> 4, c4 = (f & 15) * 4;
            float4 v = make_float4(0.f, 0.f, 0.f, 0.f);
            if (row0 + r < M) v = *(const float4*)(Xf + (size_t)(row0 + r) * 64 + c4);
            *(__half2*)(xsh + r * XSH + c4)     = __floats2half2_rn(v.x, v.y);
            *(__half2*)(xsh + r * XSH + c4 + 2) = __floats2half2_rn(v.z, v.w);
        }
    } else {
        asm volatile("cp.async.wait_group 1;");   // X group retired
    }
    __syncthreads();

    const int warp = tid >> 5, lane = tid & 31;
    const int wr = warp >> 1, wc = warp & 1;     // 2x2 warp grid, 64x32 tiles
    const int qr = lane >> 2, qc = lane & 3;

    // hoist A-fragments (K=64 -> 4 k-blocks; 4 m16 tiles) into 64 registers
    unsigned areg[4][4][4];
    #pragma unroll
    for (int kb = 0; kb < 4; kb++)
        #pragma unroll
        for (int mi = 0; mi < 4; mi++) {
            const __half* p = xsh + (wr * 64 + mi * 16 + qr) * XSH + kb * 16 + qc * 2;
            areg[kb][mi][0] = *(const unsigned*)(p);
            areg[kb][mi][1] = *(const unsigned*)(p + 8 * XSH);
            areg[kb][mi][2] = *(const unsigned*)(p + 8);
            areg[kb][mi][3] = *(const unsigned*)(p + 8 * XSH + 8);
        }

    for (int t = 0; t < NT; t++) {
        if (t + 1 < NT) {
            const int coln = (blockIdx.y * NT + t + 1) * 64;
            unsigned wd = wu[(t + 1) & 1];
            #pragma unroll
            for (int i = 0; i < 4; i++) {
                int f = tid + i * 128, r = f >> 3, c8 = (f & 7) * 8;
                cp16(wd + (unsigned)(r * KSH + c8) * 2,
                     Wt + (size_t)(coln + r) * 64 + c8);
            }
            asm volatile("cp.async.commit_group;");
            asm volatile("cp.async.wait_group 1;");
        } else {
            asm volatile("cp.async.wait_group 0;");
        }
        __syncthreads();

        const __half* wt = wtb[t & 1];
        float acc[4][4][4];
        #pragma unroll
        for (int mi = 0; mi < 4; mi++)
            #pragma unroll
            for (int ni = 0; ni < 4; ni++)
                #pragma unroll
                for (int s = 0; s < 4; s++) acc[mi][ni][s] = 0.f;

        #pragma unroll
        for (int kb = 0; kb < 4; kb++) {
            unsigned b[4][2];
            #pragma unroll
            for (int ni = 0; ni < 4; ni++) {
                const __half* p = wt + (wc * 32 + ni * 8 + qr) * KSH + kb * 16 + qc * 2;
                b[ni][0] = *(const unsigned*)(p);
                b[ni][1] = *(const unsigned*)(p + 8);
            }
            #pragma unroll
            for (int mi = 0; mi < 4; mi++)
                #pragma unroll
                for (int ni = 0; ni < 4; ni++)
                    asm volatile(
                        "mma.sync.aligned.m16n8k16.row.col.f32.f16.f16.f32 "
                        "{%0,%1,%2,%3}, {%4,%5,%6,%7}, {%8,%9}, {%0,%1,%2,%3};"
                        : "+f"(acc[mi][ni][0]), "+f"(acc[mi][ni][1]),
                          "+f"(acc[mi][ni][2]), "+f"(acc[mi][ni][3])
                        : "r"(areg[kb][mi][0]), "r"(areg[kb][mi][1]),
                          "r"(areg[kb][mi][2]), "r"(areg[kb][mi][3]),
                          "r"(b[ni][0]), "r"(b[ni][1]));
        }
        __syncthreads();

        const int col0 = (blockIdx.y * NT + t) * 64;
        #pragma unroll
        for (int mi = 0; mi < 4; mi++)
            #pragma unroll
            for (int half = 0; half < 2; half++) {
                int row = row0 + wr * 64 + mi * 16 + qr + half * 8;
                if (row < M) {
                    #pragma unroll
                    for (int ni = 0; ni < 4; ni++) {
                        int col = col0 + wc * 32 + ni * 8 + qc * 2;
                        float vx = acc[mi][ni][half * 2 + 0];
                        float vy = acc[mi][ni][half * 2 + 1];
                        if (bias) {
                            float2 bv = *(const float2*)(bias + col);
                            vx += bv.x; vy += bv.y;
                        }
                        if (HALF_OUT) {
                            *(__half2*)((__half*)Cv + (size_t)row * Nout + col) =
                                __floats2half2_rn(vx, vy);
                        } else {
                            *(float2*)((float*)Cv + (size_t)row * Nout + col) =
                                make_float2(vx, vy);
                        }
                    }
                }
            }
    }
}

// ---------------- encoder gather-max + bias + leaky_relu(0.2) ----------------
__global__ void __launch_bounds__(256)
gather_enc(const int* __restrict__ src, const float* __restrict__ b) {
    __shared__ int ss[32];
    int tid = threadIdx.x;
    if (tid < 32) ss[tid] = src[blockIdx.x * 32 + tid];
    __syncthreads();
    int local = tid >> 6;
    int j     = tid & 63;
    int node  = blockIdx.x * 4 + local;
    float a = __half2float(__ldcs(g_AB1h + (size_t)node * 128 + j));
    float m = -3.4e38f;
    #pragma unroll
    for (int k = 0; k < KNN; k++) {
        int s = ss[local * 8 + k];
        m = fmaxf(m, __half2float(g_AB1h[(size_t)s * 128 + 64 + j]));
    }
    float v = a + m + b[j];
    v = v > 0.f ? v : 0.2f * v;
    g_hh[(size_t)node * 64 + j] = __float2half_rn(v);
}

// ---------------- mean/logvar gather-max + reparametrize (pre-shuffled) --------
__global__ void __launch_bounds__(256)
gather_ml(const int* __restrict__ src, const float* __restrict__ noise) {
    __shared__ int ss[KNN];
    int tid  = threadIdx.x;
    int node = blockIdx.x;
    if (tid < KNN) ss[tid] = src[node * KNN + tid];
    __syncthreads();
    size_t abase = (size_t)node * 1024;
    float am  = __half2float(__ldcs(g_AB2h + abase + tid));
    float alv = __half2float(__ldcs(g_AB2h + abase + 256 + tid));
    float mm = -3.4e38f, mlv = -3.4e38f;
    #pragma unroll
    for (int k = 0; k < KNN; k++) {
        size_t sb = (size_t)ss[k] * 1024 + 512;
        mm  = fmaxf(mm,  __half2float(g_AB2h[sb + tid]));
        mlv = fmaxf(mlv, __half2float(g_AB2h[sb + 256 + tid]));
    }
    float zm  = am  + mm  + g_bmp[tid];
    float zlv = alv + mlv + g_blvp[tid];
    size_t o = (size_t)node * 256 + tid;
    float nz = __ldcs(noise + o);
    g_zh[o] = __float2half_rn(fmaf(nz, expf(0.5f * zlv), zm));
}

// ---------------- launch ----------------
extern "C" void kernel_launch(void* const* d_in, const int* in_sizes, int n_in,
                              void* d_out, int out_size) {
    const float* x     = (const float*)d_in[0];
    const int*   src   = (const int*)  d_in[1];
    const float* noise = (const float*)d_in[3];
    const float* We    = (const float*)d_in[4];
    const float* be    = (const float*)d_in[5];
    const float* Wm    = (const float*)d_in[6];
    const float* bm    = (const float*)d_in[7];
    const float* Wlv   = (const float*)d_in[8];
    const float* blv   = (const float*)d_in[9];
    const float* Wd    = (const float*)d_in[10];
    const float* bd    = (const float*)d_in[11];
    float* out = (float*)d_out;

    __half *pWcE, *pWAB, *pWdt, *pAB1, *pH, *pAB2, *pZ;
    cudaGetSymbolAddress((void**)&pWcE, g_WcE_h);
    cudaGetSymbolAddress((void**)&pWAB, g_WAB_h);
    cudaGetSymbolAddress((void**)&pWdt, g_Wdt_h);
    cudaGetSymbolAddress((void**)&pAB1, g_AB1h);
    cudaGetSymbolAddress((void**)&pH,   g_hh);
    cudaGetSymbolAddress((void**)&pAB2, g_AB2h);
    cudaGetSymbolAddress((void**)&pZ,   g_zh);

    // 1. combined weights (fp16, n-major, shuffle-permuted)
    prep_weights<<<307, 256>>>(We, Wm, Wlv, Wd, bm, blv);
    // 2. AB1 = x @ [A_enc | B_enc]   (50000 x 128, fp16 out)
    gemm16<2, false, true><<<dim3(391, 1), 128>>>(x, pWcE, pAB1, N_NODES, 128, nullptr);
    // 3. h = leaky(A + max_k B[src] + b)   (fp16)
    gather_enc<<<12500, 256>>>(src, be);
    // 4. AB2 = h @ [Am'|Alv'|Bm'|Blv']  (50000 x 1024, fp16)
    gemm16<8, true, true><<<dim3(391, 2), 128>>>(pH, pWAB, pAB2, N_NODES, 1024, nullptr);
    // 5. gather-max x2 + reparametrize -> z (fp16, contiguous)
    gather_ml<<<N_NODES, 256>>>(src, noise);
    // 6. out = z @ W_dec + b_dec
    gemm16<1, true, false><<<dim3(NT_DEC, 1), 128>>>(pZ, pWdt, out, NR, 64, bd);
}

// round 14
// speedup vs baseline: 1.8487x; 1.3366x over previous
#include <cuda_runtime.h>
#include <cuda_fp16.h>
#include <math.h>

#define N_NODES 50000
#define N_PAD   50048    // padded to 128-row tiles (391*128)
#define KNN     8
#define NR      200000   // N * R
#define NT_DEC  1563     // ceil(NR/128)

// ---------------- scratch (device globals) ----------------
// All weights fp16, n-major [n][64k] so B-fragments load contiguously.
__device__ __half g_WcE_h[128 * 64];                 // [n][k]: n<64 own(A), n>=64 neighbor(B)
__device__ __half g_WAB_h[1024 * 64];                // [n][k], shuffle-permuted
__device__ __half g_Wdt_h[64 * 64];                  // [n][k] decoder
__device__ float  g_bmp [256];                       // permuted biases
__device__ float  g_blvp[256];
__device__ __half g_AB1h[(size_t)N_NODES * 128];     // [node][ own(64) | nb(64) ]
__device__ __half g_hh  [(size_t)N_PAD * 64];        // fp16 h, zero-padded rows
__device__ __half g_AB2h[(size_t)N_NODES * 1024];    // [ own(512) | neighbor(512) ]
__device__ __half g_zh  [(size_t)NT_DEC * 128 * 64]; // fp16 z, padded to full tiles

// ---------------- weight prep (fp16, n-major, shuffle-permuted) ----------------
// concat([xi, xj-xi]) @ W == xi @ (W_top - W_bot) + xj @ W_bot
// sigma(p)=(p&63)*4+(p>>6) bakes point_shuffle into mean/logvar columns.
__global__ void prep_weights(const float* __restrict__ We,
                             const float* __restrict__ Wm,
                             const float* __restrict__ Wlv,
                             const float* __restrict__ Wd,
                             const float* __restrict__ bm,
                             const float* __restrict__ blv) {
    int idx = blockIdx.x * blockDim.x + threadIdx.x;
    if (idx < 128 * 64) {                            // encoder: [n][k]
        int n = idx >> 6, k = idx & 63;
        float v = (n < 64) ? We[k * 64 + n] - We[(64 + k) * 64 + n]
                           : We[(64 + k) * 64 + (n - 64)];
        g_WcE_h[idx] = __float2half_rn(v);
    }
    int i2 = idx - 128 * 64;
    if (i2 >= 0 && i2 < 1024 * 64) {                 // mean/logvar: [n][k]
        int n = i2 >> 6, k = i2 & 63;
        int half = n >> 9;                           // 0 = own(A), 1 = neighbor(B)
        int cc   = n & 511;
        const float* Wsrc = (cc < 256) ? Wm : Wlv;
        int j  = cc & 255;
        int ch = ((j & 63) << 2) | (j >> 6);         // sigma
        float v;
        if (half == 0) v = Wsrc[k * 256 + ch] - Wsrc[(64 + k) * 256 + ch];
        else           v = Wsrc[(64 + k) * 256 + ch];
        g_WAB_h[i2] = __float2half_rn(v);
    }
    int i3 = idx - 128 * 64 - 1024 * 64;
    if (i3 >= 0 && i3 < 64 * 64) {                   // decoder transpose: [n][k]
        int n = i3 >> 6, k = i3 & 63;
        g_Wdt_h[i3] = __float2half_rn(Wd[k * 64 + n]);
    }
    int i4 = idx - 128 * 64 - 1024 * 64 - 64 * 64;
    if (i4 >= 0 && i4 < 512) {
        int p = i4 & 255;
        int ch = ((p & 63) << 2) | (p >> 6);
        if (i4 < 256) g_bmp[p]  = bm[ch];
        else          g_blvp[p] = blv[ch];
    }
}

// ---------------- fp16 tensor-core GEMM (m16n8k16), 64x32 warp tiles ----------
// C[M,Nout] = X[M,64] @ Wt^T (+bias), Wt n-major [Nout][64] fp16.
// 128 rows x (NT*64) cols per block, 4 warps (2x2), 64x32 per warp.
#define XSH 72   // halves per X row  (bank = 4*qr+qc: conflict-free frags)
#define KSH 72   // halves per Wt row

__device__ __forceinline__ void cp16(unsigned dst, const void* src) {
    asm volatile("cp.async.ca.shared.global [%0], [%1], 16;" :: "r"(dst), "l"(src));
}

template<int NT, bool HALF_IN, bool HALF_OUT>
__global__ void __launch_bounds__(128, 3)
gemm16(const void* __restrict__ Xv, const __half* __restrict__ Wt,
       void* __restrict__ Cv, int M, int Nout, const float* __restrict__ bias)
{
    __shared__ __half xsh[128 * XSH];
    __shared__ __half wtb[2][64 * KSH];
    const unsigned xu = (unsigned)__cvta_generic_to_shared(xsh);
    const unsigned wu[2] = { (unsigned)__cvta_generic_to_shared(wtb[0]),
                             (unsigned)__cvta_generic_to_shared(wtb[1]) };

    const int tid  = threadIdx.x;
    const int row0 = blockIdx.x * 128;

    if (HALF_IN) {   // input padded to full 128-row tiles -> raw async copy
        const __half* Xh = (const __half*)Xv;
        #pragma unroll
        for (int i = 0; i < 8; i++) {
            int f = tid + i * 128, r = f >> 3, c8 = (f & 7) * 8;
            cp16(xu + (unsigned)(r * XSH + c8) * 2,
                 Xh + (size_t)row0 * 64 + r * 64 + c8);
        }
        asm volatile("cp.async.commit_group;");
    }
    {   // prefetch W tile 0 (rows col0..col0+63 of n-major Wt)
        const int col0 = blockIdx.y * NT * 64;
        #pragma unroll
        for (int i = 0; i < 4; i++) {
            int f = tid + i * 128, r = f >> 3, c8 = (f & 7) * 8;
            cp16(wu[0] + (unsigned)(r * KSH + c8) * 2,
                 Wt + (size_t)(col0 + r) * 64 + c8);
        }
        asm volatile("cp.async.commit_group;");
    }
    if (!HALF_IN) {  // fp32 input: load + convert (row-guarded)
        const float* Xf = (const float*)Xv;
        #pragma unroll
        for (int i = 0; i < 16; i++) {
            int f = tid + i * 128, r = f >> 4, c4 = (f & 15) * 4;
            float4 v = make_float4(0.f, 0.f, 0.f, 0.f);
            if (row0 + r < M) v = *(const float4*)(Xf + (size_t)(row0 + r) * 64 + c4);
            *(__half2*)(xsh + r * XSH + c4)     = __floats2half2_rn(v.x, v.y);
            *(__half2*)(xsh + r * XSH + c4 + 2) = __floats2half2_rn(v.z, v.w);
        }
    } else {
        asm volatile("cp.async.wait_group 1;");   // X group retired
    }
    __syncthreads();

    const int warp = tid >> 5, lane = tid & 31;
    const int wr = warp >> 1, wc = warp & 1;     // 2x2 warp grid, 64x32 tiles
    const int qr = lane >> 2, qc = lane & 3;

    // hoist A-fragments (K=64 -> 4 k-blocks; 4 m16 tiles) into 64 registers
    unsigned areg[4][4][4];
    #pragma unroll
    for (int kb = 0; kb < 4; kb++)
        #pragma unroll
        for (int mi = 0; mi < 4; mi++) {
            const __half* p = xsh + (wr * 64 + mi * 16 + qr) * XSH + kb * 16 + qc * 2;
            areg[kb][mi][0] = *(const unsigned*)(p);
            areg[kb][mi][1] = *(const unsigned*)(p + 8 * XSH);
            areg[kb][mi][2] = *(const unsigned*)(p + 8);
            areg[kb][mi][3] = *(const unsigned*)(p + 8 * XSH + 8);
        }

    for (int t = 0; t < NT; t++) {
        if (t + 1 < NT) {
            const int coln = (blockIdx.y * NT + t + 1) * 64;
            unsigned wd = wu[(t + 1) & 1];
            #pragma unroll
            for (int i = 0; i < 4; i++) {
                int f = tid + i * 128, r = f >> 3, c8 = (f & 7) * 8;
                cp16(wd + (unsigned)(r * KSH + c8) * 2,
                     Wt + (size_t)(coln + r) * 64 + c8);
            }
            asm volatile("cp.async.commit_group;");
            asm volatile("cp.async.wait_group 1;");
        } else {
            asm volatile("cp.async.wait_group 0;");
        }
        __syncthreads();

        const __half* wt = wtb[t & 1];
        float acc[4][4][4];
        #pragma unroll
        for (int mi = 0; mi < 4; mi++)
            #pragma unroll
            for (int ni = 0; ni < 4; ni++)
                #pragma unroll
                for (int s = 0; s < 4; s++) acc[mi][ni][s] = 0.f;

        #pragma unroll
        for (int kb = 0; kb < 4; kb++) {
            unsigned b[4][2];
            #pragma unroll
            for (int ni = 0; ni < 4; ni++) {
                const __half* p = wt + (wc * 32 + ni * 8 + qr) * KSH + kb * 16 + qc * 2;
                b[ni][0] = *(const unsigned*)(p);
                b[ni][1] = *(const unsigned*)(p + 8);
            }
            #pragma unroll
            for (int mi = 0; mi < 4; mi++)
                #pragma unroll
                for (int ni = 0; ni < 4; ni++)
                    asm volatile(
                        "mma.sync.aligned.m16n8k16.row.col.f32.f16.f16.f32 "
                        "{%0,%1,%2,%3}, {%4,%5,%6,%7}, {%8,%9}, {%0,%1,%2,%3};"
                        : "+f"(acc[mi][ni][0]), "+f"(acc[mi][ni][1]),
                          "+f"(acc[mi][ni][2]), "+f"(acc[mi][ni][3])
                        : "r"(areg[kb][mi][0]), "r"(areg[kb][mi][1]),
                          "r"(areg[kb][mi][2]), "r"(areg[kb][mi][3]),
                          "r"(b[ni][0]), "r"(b[ni][1]));
        }
        __syncthreads();

        const int col0 = (blockIdx.y * NT + t) * 64;
        #pragma unroll
        for (int mi = 0; mi < 4; mi++)
            #pragma unroll
            for (int half = 0; half < 2; half++) {
                int row = row0 + wr * 64 + mi * 16 + qr + half * 8;
                if (row < M) {
                    #pragma unroll
                    for (int ni = 0; ni < 4; ni++) {
                        int col = col0 + wc * 32 + ni * 8 + qc * 2;
                        float vx = acc[mi][ni][half * 2 + 0];
                        float vy = acc[mi][ni][half * 2 + 1];
                        if (bias) {
                            float2 bv = *(const float2*)(bias + col);
                            vx += bv.x; vy += bv.y;
                        }
                        if (HALF_OUT) {
                            *(__half2*)((__half*)Cv + (size_t)row * Nout + col) =
                                __floats2half2_rn(vx, vy);
                        } else {
                            *(float2*)((float*)Cv + (size_t)row * Nout + col) =
                                make_float2(vx, vy);
                        }
                    }
                }
            }
    }
}

// ---------------- encoder gather-max + bias + leaky_relu (half2) --------------
// 8 nodes/block, 256 threads; thread handles channel pair 2*j2, 2*j2+1.
__global__ void __launch_bounds__(256)
gather_enc(const int* __restrict__ src, const float* __restrict__ b) {
    __shared__ int ss[64];
    int tid = threadIdx.x;
    if (tid < 64) ss[tid] = src[blockIdx.x * 64 + tid];
    __syncthreads();
    int local = tid >> 5;                    // 0..7
    int j2    = tid & 31;                    // half2 channel index
    int node  = blockIdx.x * 8 + local;
    const __half2* AB1 = (const __half2*)g_AB1h;   // row = 64 half2
    __half2 a2 = __ldcs(AB1 + (size_t)node * 64 + j2);
    __half2 m2 = __float2half2_rn(-60000.f);
    #pragma unroll
    for (int k = 0; k < KNN; k++) {
        int s = ss[local * 8 + k];
        m2 = __hmax2(m2, AB1[(size_t)s * 64 + 32 + j2]);
    }
    float2 bv = *(const float2*)(b + j2 * 2);
    float vx = __half2float(__low2half(a2))  + __half2float(__low2half(m2))  + bv.x;
    float vy = __half2float(__high2half(a2)) + __half2float(__high2half(m2)) + bv.y;
    vx = vx > 0.f ? vx : 0.2f * vx;
    vy = vy > 0.f ? vy : 0.2f * vy;
    ((__half2*)g_hh)[(size_t)node * 32 + j2] = __floats2half2_rn(vx, vy);
}

// ---------------- mean/logvar gather-max + reparametrize (half2) --------------
// 2 nodes/block, 256 threads; thread handles channel pair 2*c2, 2*c2+1.
// AB2 half2 row (512): own mean [0,128) | own lv [128,256) | nb mean [256,384) | nb lv [384,512)
__global__ void __launch_bounds__(256)
gather_ml(const int* __restrict__ src, const float* __restrict__ noise) {
    __shared__ int ss[16];
    int tid = threadIdx.x;
    if (tid < 16) ss[tid] = src[blockIdx.x * 16 + tid];
    __syncthreads();
    int local = tid >> 7;                    // 0..1
    int c2    = tid & 127;                   // half2 channel index
    int node  = blockIdx.x * 2 + local;
    const __half2* AB2 = (const __half2*)g_AB2h;   // row = 512 half2
    size_t abase = (size_t)node * 512;
    __half2 am2  = __ldcs(AB2 + abase + c2);
    __half2 alv2 = __ldcs(AB2 + abase + 128 + c2);
    __half2 mm2  = __float2half2_rn(-60000.f);
    __half2 mlv2 = __float2half2_rn(-60000.f);
    #pragma unroll
    for (int k = 0; k < KNN; k++) {
        size_t sb = (size_t)ss[local * 8 + k] * 512 + 256;
        mm2  = __hmax2(mm2,  AB2[sb + c2]);
        mlv2 = __hmax2(mlv2, AB2[sb + 128 + c2]);
    }
    float2 bmv  = *(const float2*)(g_bmp  + c2 * 2);
    float2 blvv = *(const float2*)(g_blvp + c2 * 2);
    float zmx  = __half2float(__low2half(am2))  + __half2float(__low2half(mm2))  + bmv.x;
    float zmy  = __half2float(__high2half(am2)) + __half2float(__high2half(mm2)) + bmv.y;
    float zlx  = __half2float(__low2half(alv2))  + __half2float(__low2half(mlv2))  + blvv.x;
    float zly  = __half2float(__high2half(alv2)) + __half2float(__high2half(mlv2)) + blvv.y;
    size_t o2 = (size_t)node * 128 + c2;
    float2 nz = __ldcs((const float2*)noise + o2);
    float zx = fmaf(nz.x, expf(0.5f * zlx), zmx);
    float zy = fmaf(nz.y, expf(0.5f * zly), zmy);
    ((__half2*)g_zh)[o2] = __floats2half2_rn(zx, zy);
}

// ---------------- launch ----------------
extern "C" void kernel_launch(void* const* d_in, const int* in_sizes, int n_in,
                              void* d_out, int out_size) {
    const float* x     = (const float*)d_in[0];
    const int*   src   = (const int*)  d_in[1];
    const float* noise = (const float*)d_in[3];
    const float* We    = (const float*)d_in[4];
    const float* be    = (const float*)d_in[5];
    const float* Wm    = (const float*)d_in[6];
    const float* bm    = (const float*)d_in[7];
    const float* Wlv   = (const float*)d_in[8];
    const float* blv   = (const float*)d_in[9];
    const float* Wd    = (const float*)d_in[10];
    const float* bd    = (const float*)d_in[11];
    float* out = (float*)d_out;

    __half *pWcE, *pWAB, *pWdt, *pAB1, *pH, *pAB2, *pZ;
    cudaGetSymbolAddress((void**)&pWcE, g_WcE_h);
    cudaGetSymbolAddress((void**)&pWAB, g_WAB_h);
    cudaGetSymbolAddress((void**)&pWdt, g_Wdt_h);
    cudaGetSymbolAddress((void**)&pAB1, g_AB1h);
    cudaGetSymbolAddress((void**)&pH,   g_hh);
    cudaGetSymbolAddress((void**)&pAB2, g_AB2h);
    cudaGetSymbolAddress((void**)&pZ,   g_zh);

    // 1. combined weights (fp16, n-major, shuffle-permuted)
    prep_weights<<<307, 256>>>(We, Wm, Wlv, Wd, bm, blv);
    // 2. AB1 = x @ [A_enc | B_enc]   (50000 x 128, fp16 out)
    gemm16<2, false, true><<<dim3(391, 1), 128>>>(x, pWcE, pAB1, N_NODES, 128, nullptr);
    // 3. h = leaky(A + max_k B[src] + b)   (fp16, half2)
    gather_enc<<<6250, 256>>>(src, be);
    // 4. AB2 = h @ [Am'|Alv'|Bm'|Blv']  (50000 x 1024, fp16)
    gemm16<8, true, true><<<dim3(391, 2), 128>>>(pH, pWAB, pAB2, N_NODES, 1024, nullptr);
    // 5. gather-max x2 + reparametrize -> z (fp16, half2, contiguous)
    gather_ml<<<25000, 256>>>(src, noise);
    // 6. out = z @ W_dec + b_dec
    gemm16<1, true, false><<<dim3(NT_DEC, 1), 128>>>(pZ, pWdt, out, NR, 64, bd);
}

// round 17
// speedup vs baseline: 2.0681x; 1.1186x over previous
#include <cuda_runtime.h>
#include <cuda_fp16.h>
#include <math.h>

#define N_NODES 50000
#define N_PAD   50048    // padded to 128-row tiles (391*128)
#define KNN     8
#define NR      200000   // N * R
#define NT_DEC  1563     // ceil(NR/128)

// ---------------- scratch (device globals) ----------------
__device__ __half g_WcE_h[128 * 64];                 // [n][k], epilogue-permuted
__device__ __half g_WAB_h[1024 * 64];                // [n][k], shuffle+epilogue-permuted
__device__ __half g_Wdt_h[64 * 64];                  // [n][k] decoder (true order)
__device__ float  g_bmp [256];                       // permuted biases
__device__ float  g_blvp[256];
__device__ __half g_AB1h[(size_t)N_NODES * 128];     // [node][ own(64) | nb(64) ]
__device__ __half g_hh  [(size_t)N_PAD * 64];        // fp16 h, zero-padded rows
__device__ __half g_AB2h[(size_t)N_NODES * 1024];    // [ own(512) | neighbor(512) ]
__device__ __half g_zh  [(size_t)NT_DEC * 128 * 64]; // fp16 z, padded to full tiles

// epilogue permutation within a 64-col tile: swap ni(bits4:3) <-> qc(bits2:1).
// Involution. MMA column n's result is STORED at position pi64(n); so weight
// column n must carry the channel belonging at stored position pi64(n).
__host__ __device__ __forceinline__ int pi64(int c) {
    return (c & 0x21) | ((c & 0x06) << 2) | ((c & 0x18) >> 2);
}

// ---------------- weight prep (fp16, n-major, shuffle+epi-permuted) -----------
// concat([xi, xj-xi]) @ W == xi @ (W_top - W_bot) + xj @ W_bot
// sigma(p)=(p&63)*4+(p>>6) bakes point_shuffle into mean/logvar positions.
__global__ void prep_weights(const float* __restrict__ We,
                             const float* __restrict__ Wm,
                             const float* __restrict__ Wlv,
                             const float* __restrict__ Wd,
                             const float* __restrict__ bm,
                             const float* __restrict__ blv) {
    int idx = blockIdx.x * blockDim.x + threadIdx.x;
    if (idx < 128 * 64) {                            // encoder: [n][k]
        int n0 = idx >> 6, k = idx & 63;
        int n = (n0 & 64) | pi64(n0 & 63);           // stored position this col feeds
        float v = (n < 64) ? We[k * 64 + n] - We[(64 + k) * 64 + n]
                           : We[(64 + k) * 64 + (n - 64)];
        g_WcE_h[idx] = __float2half_rn(v);
    }
    int i2 = idx - 128 * 64;
    if (i2 >= 0 && i2 < 1024 * 64) {                 // mean/logvar: [n][k]
        int n0 = i2 >> 6, k = i2 & 63;
        int n = (n0 & ~63) | pi64(n0 & 63);          // stored position
        int half = n >> 9;                           // 0 = own(A), 1 = neighbor(B)
        int cc   = n & 511;
        const float* Wsrc = (cc < 256) ? Wm : Wlv;
        int j  = cc & 255;
        int ch = ((j & 63) << 2) | (j >> 6);         // sigma
        float v;
        if (half == 0) v = Wsrc[k * 256 + ch] - Wsrc[(64 + k) * 256 + ch];
        else           v = Wsrc[(64 + k) * 256 + ch];
        g_WAB_h[i2] = __float2half_rn(v);
    }
    int i3 = idx - 128 * 64 - 1024 * 64;
    if (i3 >= 0 && i3 < 64 * 64) {                   // decoder transpose: [n][k]
        int n = i3 >> 6, k = i3 & 63;
        g_Wdt_h[i3] = __float2half_rn(Wd[k * 64 + n]);
    }
    int i4 = idx - 128 * 64 - 1024 * 64 - 64 * 64;
    if (i4 >= 0 && i4 < 512) {
        int p = i4 & 255;
        int ch = ((p & 63) << 2) | (p >> 6);
        if (i4 < 256) g_bmp[p]  = bm[ch];
        else          g_blvp[p] = blv[ch];
    }
}

// ---------------- fp16 tensor-core GEMM (m16n8k16), 64x32 warp tiles ----------
// C[M,Nout] = X[M,64] @ Wt^T (+bias), Wt n-major [Nout][64] fp16.
// 128 rows x (NT*64) cols per block, 4 warps (2x2), 64x32 per warp.
// HALF_OUT path: weights are pi64-permuted -> one 16B store per (mi,half).
#define XSH 72   // halves per X row  (bank = 4*qr+qc: conflict-free frags)
#define KSH 72   // halves per Wt row

__device__ __forceinline__ void cp16(unsigned dst, const void* src) {
    asm volatile("cp.async.ca.shared.global [%0], [%1], 16;" :: "r"(dst), "l"(src));
}

template<int NT, bool HALF_IN, bool HALF_OUT>
__global__ void __launch_bounds__(128, 3)
gemm16(const void* __restrict__ Xv, const __half* __restrict__ Wt,
       void* __restrict__ Cv, int M, int Nout, const float* __restrict__ bias)
{
    __shared__ __half xsh[128 * XSH];
    __shared__ __half wtb[2][64 * KSH];
    const unsigned xu = (unsigned)__cvta_generic_to_shared(xsh);
    const unsigned wu[2] = { (unsigned)__cvta_generic_to_shared(wtb[0]),
                             (unsigned)__cvta_generic_to_shared(wtb[1]) };

    const int tid  = threadIdx.x;
    const int row0 = blockIdx.x * 128;

    if (HALF_IN) {   // input padded to full 128-row tiles -> raw async copy
        const __half* Xh = (const __half*)Xv;
        #pragma unroll
        for (int i = 0; i < 8; i++) {
            int f = tid + i * 128, r = f >> 3, c8 = (f & 7) * 8;
            cp16(xu + (unsigned)(r * XSH + c8) * 2,
                 Xh + (size_t)row0 * 64 + r * 64 + c8);
        }
        asm volatile("cp.async.commit_group;");
    }
    {   // prefetch W tile 0 (rows col0..col0+63 of n-major Wt)
        const int col0 = blockIdx.y * NT * 64;
        #pragma unroll
        for (int i = 0; i < 4; i++) {
            int f = tid + i * 128, r = f >> 3, c8 = (f & 7) * 8;
            cp16(wu[0] + (unsigned)(r * KSH + c8) * 2,
                 Wt + (size_t)(col0 + r) * 64 + c8);
        }
        asm volatile("cp.async.commit_group;");
    }
    if (!HALF_IN) {  // fp32 input: load + convert (row-guarded)
        const float* Xf = (const float*)Xv;
        #pragma unroll
        for (int i = 0; i < 16; i++) {
            int f = tid + i * 128, r = f >> 4, c4 = (f & 15) * 4;
            float4 v = make_float4(0.f, 0.f, 0.f, 0.f);
            if (row0 + r < M) v = *(const float4*)(Xf + (size_t)(row0 + r) * 64 + c4);
            *(__half2*)(xsh + r * XSH + c4)     = __floats2half2_rn(v.x, v.y);
            *(__half2*)(xsh + r * XSH + c4 + 2) = __floats2half2_rn(v.z, v.w);
        }
    } else {
        asm volatile("cp.async.wait_group 1;");   // X group retired
    }
    __syncthreads();

    const int warp = tid >> 5, lane = tid & 31;
    const int wr = warp >> 1, wc = warp & 1;     // 2x2 warp grid, 64x32 tiles
    const int qr = lane >> 2, qc = lane & 3;

    // hoist A-fragments (K=64 -> 4 k-blocks; 4 m16 tiles) into 64 registers
    unsigned areg[4][4][4];
    #pragma unroll
    for (int kb = 0; kb < 4; kb++)
        #pragma unroll
        for (int mi = 0; mi < 4; mi++) {
            const __half* p = xsh + (wr * 64 + mi * 16 + qr) * XSH + kb * 16 + qc * 2;
            areg[kb][mi][0] = *(const unsigned*)(p);
            areg[kb][mi][1] = *(const unsigned*)(p + 8 * XSH);
            areg[kb][mi][2] = *(const unsigned*)(p + 8);
            areg[kb][mi][3] = *(const unsigned*)(p + 8 * XSH + 8);
        }

    for (int t = 0; t < NT; t++) {
        if (t + 1 < NT) {
            const int coln = (blockIdx.y * NT + t + 1) * 64;
            unsigned wd = wu[(t + 1) & 1];
            #pragma unroll
            for (int i = 0; i < 4; i++) {
                int f = tid + i * 128, r = f >> 3, c8 = (f & 7) * 8;
                cp16(wd + (unsigned)(r * KSH + c8) * 2,
                     Wt + (size_t)(coln + r) * 64 + c8);
            }
            asm volatile("cp.async.commit_group;");
            asm volatile("cp.async.wait_group 1;");
        } else {
            asm volatile("cp.async.wait_group 0;");
        }
        __syncthreads();

        const __half* wt = wtb[t & 1];
        float acc[4][4][4];
        #pragma unroll
        for (int mi = 0; mi < 4; mi++)
            #pragma unroll
            for (int ni = 0; ni < 4; ni++)
                #pragma unroll
                for (int s = 0; s < 4; s++) acc[mi][ni][s] = 0.f;

        #pragma unroll
        for (int kb = 0; kb < 4; kb++) {
            unsigned b[4][2];
            #pragma unroll
            for (int ni = 0; ni < 4; ni++) {
                const __half* p = wt + (wc * 32 + ni * 8 + qr) * KSH + kb * 16 + qc * 2;
                b[ni][0] = *(const unsigned*)(p);
                b[ni][1] = *(const unsigned*)(p + 8);
            }
            #pragma unroll
            for (int mi = 0; mi < 4; mi++)
                #pragma unroll
                for (int ni = 0; ni < 4; ni++)
                    asm volatile(
                        "mma.sync.aligned.m16n8k16.row.col.f32.f16.f16.f32 "
                        "{%0,%1,%2,%3}, {%4,%5,%6,%7}, {%8,%9}, {%0,%1,%2,%3};"
                        : "+f"(acc[mi][ni][0]), "+f"(acc[mi][ni][1]),
                          "+f"(acc[mi][ni][2]), "+f"(acc[mi][ni][3])
                        : "r"(areg[kb][mi][0]), "r"(areg[kb][mi][1]),
                          "r"(areg[kb][mi][2]), "r"(areg[kb][mi][3]),
                          "r"(b[ni][0]), "r"(b[ni][1]));
        }
        __syncthreads();

        const int col0 = (blockIdx.y * NT + t) * 64;
        if (HALF_OUT) {
            // weights pi64-permuted: this thread's 4 half2s (ni=0..3) belong at
            // contiguous stored positions col0 + wc*32 + qc*8 .. +7 -> one 16B store.
            #pragma unroll
            for (int mi = 0; mi < 4; mi++)
                #pragma unroll
                for (int half = 0; half < 2; half++) {
                    int row = row0 + wr * 64 + mi * 16 + qr + half * 8;
                    if (row < M) {
                        __half2 pk[4];
                        #pragma unroll
                        for (int ni = 0; ni < 4; ni++)
                            pk[ni] = __floats2half2_rn(acc[mi][ni][half * 2 + 0],
                                                       acc[mi][ni][half * 2 + 1]);
                        *(float4*)((__half*)Cv + (size_t)row * Nout
                                   + col0 + wc * 32 + qc * 8) = *(float4*)pk;
                    }
                }
        } else {
            #pragma unroll
            for (int mi = 0; mi < 4; mi++)
                #pragma unroll
                for (int half = 0; half < 2; half++) {
                    int row = row0 + wr * 64 + mi * 16 + qr + half * 8;
                    if (row < M) {
                        #pragma unroll
                        for (int ni = 0; ni < 4; ni++) {
                            int col = col0 + wc * 32 + ni * 8 + qc * 2;
                            float vx = acc[mi][ni][half * 2 + 0];
                            float vy = acc[mi][ni][half * 2 + 1];
                            if (bias) {
                                float2 bv = *(const float2*)(bias + col);
                                vx += bv.x; vy += bv.y;
                            }
                            *(float2*)((float*)Cv + (size_t)row * Nout + col) =
                                make_float2(vx, vy);
                        }
                    }
                }
        }
    }
}

// ---------------- encoder gather-max + bias + leaky_relu (half2) --------------
// 8 nodes/block, 256 threads; thread handles channel pair 2*j2, 2*j2+1.
__global__ void __launch_bounds__(256)
gather_enc(const int* __restrict__ src, const float* __restrict__ b) {
    __shared__ int ss[64];
    int tid = threadIdx.x;
    if (tid < 64) ss[tid] = src[blockIdx.x * 64 + tid];
    __syncthreads();
    int local = tid >> 5;                    // 0..7
    int j2    = tid & 31;                    // half2 channel index
    int node  = blockIdx.x * 8 + local;
    const __half2* AB1 = (const __half2*)g_AB1h;   // row = 64 half2
    __half2 a2 = __ldcs(AB1 + (size_t)node * 64 + j2);
    __half2 m2 = __float2half2_rn(-60000.f);
    #pragma unroll
    for (int k = 0; k < KNN; k++) {
        int s = ss[local * 8 + k];
        m2 = __hmax2(m2, AB1[(size_t)s * 64 + 32 + j2]);
    }
    float2 bv = *(const float2*)(b + j2 * 2);
    float vx = __half2float(__low2half(a2))  + __half2float(__low2half(m2))  + bv.x;
    float vy = __half2float(__high2half(a2)) + __half2float(__high2half(m2)) + bv.y;
    vx = vx > 0.f ? vx : 0.2f * vx;
    vy = vy > 0.f ? vy : 0.2f * vy;
    ((__half2*)g_hh)[(size_t)node * 32 + j2] = __floats2half2_rn(vx, vy);
}

// ---------------- mean/logvar gather-max + reparametrize (half2) --------------
// 2 nodes/block, 256 threads; thread handles channel pair 2*c2, 2*c2+1.
// AB2 half2 row (512): own mean [0,128) | own lv [128,256) | nb mean [256,384) | nb lv [384,512)
__global__ void __launch_bounds__(256)
gather_ml(const int* __restrict__ src, const float* __restrict__ noise) {
    __shared__ int ss[16];
    int tid = threadIdx.x;
    if (tid < 16) ss[tid] = src[blockIdx.x * 16 + tid];
    __syncthreads();
    int local = tid >> 7;                    // 0..1
    int c2    = tid & 127;                   // half2 channel index
    int node  = blockIdx.x * 2 + local;
    const __half2* AB2 = (const __half2*)g_AB2h;   // row = 512 half2
    size_t abase = (size_t)node * 512;
    __half2 am2  = __ldcs(AB2 + abase + c2);
    __half2 alv2 = __ldcs(AB2 + abase + 128 + c2);
    __half2 mm2  = __float2half2_rn(-60000.f);
    __half2 mlv2 = __float2half2_rn(-60000.f);
    #pragma unroll
    for (int k = 0; k < KNN; k++) {
        size_t sb = (size_t)ss[local * 8 + k] * 512 + 256;
        mm2  = __hmax2(mm2,  AB2[sb + c2]);
        mlv2 = __hmax2(mlv2, AB2[sb + 128 + c2]);
    }
    float2 bmv  = *(const float2*)(g_bmp  + c2 * 2);
    float2 blvv = *(const float2*)(g_blvp + c2 * 2);
    float zmx  = __half2float(__low2half(am2))  + __half2float(__low2half(mm2))  + bmv.x;
    float zmy  = __half2float(__high2half(am2)) + __half2float(__high2half(mm2)) + bmv.y;
    float zlx  = __half2float(__low2half(alv2))  + __half2float(__low2half(mlv2))  + blvv.x;
    float zly  = __half2float(__high2half(alv2)) + __half2float(__high2half(mlv2)) + blvv.y;
    size_t o2 = (size_t)node * 128 + c2;
    float2 nz = __ldcs((const float2*)noise + o2);
    float zx = fmaf(nz.x, expf(0.5f * zlx), zmx);
    float zy = fmaf(nz.y, expf(0.5f * zly), zmy);
    ((__half2*)g_zh)[o2] = __floats2half2_rn(zx, zy);
}

// ---------------- launch ----------------
extern "C" void kernel_launch(void* const* d_in, const int* in_sizes, int n_in,
                              void* d_out, int out_size) {
    const float* x     = (const float*)d_in[0];
    const int*   src   = (const int*)  d_in[1];
    const float* noise = (const float*)d_in[3];
    const float* We    = (const float*)d_in[4];
    const float* be    = (const float*)d_in[5];
    const float* Wm    = (const float*)d_in[6];
    const float* bm    = (const float*)d_in[7];
    const float* Wlv   = (const float*)d_in[8];
    const float* blv   = (const float*)d_in[9];
    const float* Wd    = (const float*)d_in[10];
    const float* bd    = (const float*)d_in[11];
    float* out = (float*)d_out;

    __half *pWcE, *pWAB, *pWdt, *pAB1, *pH, *pAB2, *pZ;
    cudaGetSymbolAddress((void**)&pWcE, g_WcE_h);
    cudaGetSymbolAddress((void**)&pWAB, g_WAB_h);
    cudaGetSymbolAddress((void**)&pWdt, g_Wdt_h);
    cudaGetSymbolAddress((void**)&pAB1, g_AB1h);
    cudaGetSymbolAddress((void**)&pH,   g_hh);
    cudaGetSymbolAddress((void**)&pAB2, g_AB2h);
    cudaGetSymbolAddress((void**)&pZ,   g_zh);

    // 1. combined weights (fp16, n-major, shuffle+epi-permuted)
    prep_weights<<<307, 256>>>(We, Wm, Wlv, Wd, bm, blv);
    // 2. AB1 = x @ [A_enc | B_enc]   (50000 x 128, fp16 out, vectorized epi)
    gemm16<2, false, true><<<dim3(391, 1), 128>>>(x, pWcE, pAB1, N_NODES, 128, nullptr);
    // 3. h = leaky(A + max_k B[src] + b)   (fp16, half2)
    gather_enc<<<6250, 256>>>(src, be);
    // 4. AB2 = h @ [Am'|Alv'|Bm'|Blv']  (50000 x 1024, fp16, vectorized epi)
    gemm16<8, true, true><<<dim3(391, 2), 128>>>(pH, pWAB, pAB2, N_NODES, 1024, nullptr);
    // 5. gather-max x2 + reparametrize -> z (fp16, half2, contiguous)
    gather_ml<<<25000, 256>>>(src, noise);
    // 6. out = z @ W_dec + b_dec  (true column order)
    gemm16<1, true, false><<<dim3(NT_DEC, 1), 128>>>(pZ, pWdt, out, NR, 64, bd);
}